// round 1
// baseline (speedup 1.0000x reference)
#include <cuda_runtime.h>
#include <math.h>

#define BATCH 32
#define HW1 960
#define HW2 480
#define NB 10
#define NBLK 100
#define NTAB 9801

// ---------------- device scratch (no allocations allowed) ----------------
__device__ float g_rg[NTAB];                 // AGGD r(gamma) lookup table
__device__ float g_w7[7];                    // 1D normalized 7-tap gaussian (sigma 7/6)
__device__ float g_w3[9];                    // 2D normalized 3x3 gaussian (sigma 0.5)
__device__ float g_x2[BATCH * HW2 * HW2];    // downsampled images
__device__ float g_feats[BATCH * NBLK * 36]; // 36 features per block

static __device__ __forceinline__ unsigned long long umin64(unsigned long long a,
                                                            unsigned long long b) {
    return a < b ? a : b;
}

// ---------------- table / weight init (recomputed each launch; deterministic) ----
__global__ void init_tables_kernel() {
    int i = blockIdx.x * blockDim.x + threadIdx.x;
    if (i < NTAB) {
        double g = 0.2 + 0.001 * (double)i;
        g_rg[i] = (float)exp(2.0 * lgamma(2.0 / g) - lgamma(1.0 / g) - lgamma(3.0 / g));
    }
    if (i == 0) {
        double e[7], s = 0.0;
        double sig = 7.0 / 6.0;
        for (int j = 0; j < 7; j++) {
            double ax = (double)j - 3.0;
            e[j] = exp(-(ax * ax) / (2.0 * sig * sig));
            s += e[j];
        }
        for (int j = 0; j < 7; j++) g_w7[j] = (float)(e[j] / s);
        double e3[3], s3 = 0.0;
        for (int j = 0; j < 3; j++) {
            double ax = (double)j - 1.0;
            e3[j] = exp(-(ax * ax) / (2.0 * 0.25));
            s3 += e3[j];
        }
        double tot = s3 * s3;
        for (int a = 0; a < 3; a++)
            for (int c = 0; c < 3; c++) g_w3[a * 3 + c] = (float)(e3[a] * e3[c] / tot);
    }
}

// ---------------- downsample: 3x3 gaussian (zero pad) + stride-2 decimate ----------
__global__ void down_kernel(const float* __restrict__ X) {
    int i = blockIdx.x * blockDim.x + threadIdx.x; // 0 .. 480*480-1
    int b = blockIdx.y;
    if (i >= HW2 * HW2) return;
    int y = i / HW2, x = i - y * HW2;
    const float* im = X + (size_t)b * HW1 * HW1;
    float w[9];
#pragma unroll
    for (int k = 0; k < 9; k++) w[k] = g_w3[k];
    float s = 0.f;
#pragma unroll
    for (int di = 0; di < 3; di++) {
        int sy = 2 * y + di - 1;
        if (sy < 0 || sy >= HW1) continue;
#pragma unroll
        for (int dj = 0; dj < 3; dj++) {
            int sx = 2 * x + dj - 1;
            if (sx < 0 || sx >= HW1) continue;
            s = fmaf(w[di * 3 + dj], __ldg(&im[(size_t)sy * HW1 + sx]), s);
        }
    }
    g_x2[(size_t)b * HW2 * HW2 + i] = s;
}

// ---------------- fused per-block: MSCN normalize + AGGD features -----------------
// One CTA per 96x96 (scale1) or 48x48 (scale2) block.
template <int BS, int NTHR, bool USE_X2>
__global__ void feat_kernel(const float* __restrict__ imgIn, int HW, int foff) {
    const int TILE = BS + 6;
    const int NW = NTHR / 32;
    const int tid = threadIdx.x;
    const int blk = blockIdx.x;
    const int b = blockIdx.y;
    const int by0 = (blk / NB) * BS;
    const int bx0 = (blk - (blk / NB) * NB) * BS;

    extern __shared__ float sm[];
    float* T  = sm;                 // TILE*TILE input tile (replicate-clamped)
    float* rX  = T + TILE * TILE;   // TILE*BS row-conv of x
    float* rX2 = rX + TILE * BS;    // TILE*BS row-conv of x^2
    float* xn  = rX2 + TILE * BS;   // BS*BS normalized block

    __shared__ float s_wsum[NW][25];
    __shared__ float s_tot[25];
    __shared__ float s_rhn[5];
    __shared__ unsigned long long s_wmin[NW][5];

    float w[7];
#pragma unroll
    for (int j = 0; j < 7; j++) w[j] = g_w7[j];

    const float* im = USE_X2 ? (g_x2 + (size_t)b * HW * HW)
                             : (imgIn + (size_t)b * HW * HW);

    // load halo tile with replicate clamp (MSCN uses full-image edge padding)
    for (int idx = tid; idx < TILE * TILE; idx += NTHR) {
        int r = idx / TILE, c = idx - r * TILE;
        int gy = by0 + r - 3;
        gy = gy < 0 ? 0 : (gy >= HW ? HW - 1 : gy);
        int gx = bx0 + c - 3;
        gx = gx < 0 ? 0 : (gx >= HW ? HW - 1 : gx);
        T[idx] = im[(size_t)gy * HW + gx];
    }
    __syncthreads();

    // separable conv, horizontal pass for x and x^2
    for (int idx = tid; idx < TILE * BS; idx += NTHR) {
        int r = idx / BS, c = idx - r * BS;
        const float* tr = &T[r * TILE + c];
        float a1 = 0.f, a2 = 0.f;
#pragma unroll
        for (int j = 0; j < 7; j++) {
            float v = tr[j];
            a1 = fmaf(w[j], v, a1);
            a2 = fmaf(w[j] * v, v, a2);
        }
        rX[idx] = a1;
        rX2[idx] = a2;
    }
    __syncthreads();

    // vertical pass + MSCN
    for (int idx = tid; idx < BS * BS; idx += NTHR) {
        int r = idx / BS, c = idx - r * BS;
        float mu = 0.f, e2 = 0.f;
#pragma unroll
        for (int i2 = 0; i2 < 7; i2++) {
            mu = fmaf(w[i2], rX[(r + i2) * BS + c], mu);
            e2 = fmaf(w[i2], rX2[(r + i2) * BS + c], e2);
        }
        float sig = sqrtf(fabsf(e2 - mu * mu));
        xn[idx] = (T[(r + 3) * TILE + (c + 3)] - mu) / (sig + 1.0f);
    }
    __syncthreads();

    // 5 signals: block, and block * circular-shifted block for 4 shifts
    float acc[25];
#pragma unroll
    for (int k = 0; k < 25; k++) acc[k] = 0.f;
    for (int idx = tid; idx < BS * BS; idx += NTHR) {
        int r = idx / BS, c = idx - r * BS;
        int rm = (r == 0) ? (BS - 1) : (r - 1);
        int cm = (c == 0) ? (BS - 1) : (c - 1);
        int cp = (c == BS - 1) ? 0 : (c + 1);
        float x0 = xn[idx];
        float y[5];
        y[0] = x0;
        y[1] = x0 * xn[r * BS + cm];   // shift (0,1)
        y[2] = x0 * xn[rm * BS + c];   // shift (1,0)
        y[3] = x0 * xn[rm * BS + cm];  // shift (1,1)
        y[4] = x0 * xn[rm * BS + cp];  // shift (1,-1)
#pragma unroll
        for (int s = 0; s < 5; s++) {
            float v = y[s], v2 = v * v;
            float neg = (v < 0.f) ? 1.f : 0.f;
            float pos = (v > 0.f) ? 1.f : 0.f;
            acc[s * 5 + 0] += v2 * neg;
            acc[s * 5 + 1] += v2 * pos;
            acc[s * 5 + 2] += neg;
            acc[s * 5 + 3] += pos;
            acc[s * 5 + 4] += fabsf(v);
        }
    }
#pragma unroll
    for (int k = 0; k < 25; k++)
#pragma unroll
        for (int off = 16; off > 0; off >>= 1)
            acc[k] += __shfl_down_sync(0xffffffffu, acc[k], off);
    int warp = tid >> 5, lane = tid & 31;
    if (lane == 0) {
#pragma unroll
        for (int k = 0; k < 25; k++) s_wsum[warp][k] = acc[k];
    }
    __syncthreads();
    if (tid < 25) {
        float s = 0.f;
        for (int wi = 0; wi < NW; wi++) s += s_wsum[wi][tid];
        s_tot[tid] = s;
    }
    __syncthreads();

    float lstd = 0.f, rstd = 0.f;
    if (tid < 5) {
        float SN = s_tot[tid * 5 + 0], SP = s_tot[tid * 5 + 1];
        float CN = s_tot[tid * 5 + 2], CP = s_tot[tid * 5 + 3];
        float SA = s_tot[tid * 5 + 4];
        float cl = fmaxf(CN, 1.f), cr = fmaxf(CP, 1.f);
        lstd = sqrtf(SN / cl);
        rstd = sqrtf(SP / cr);
        float gh = lstd / fmaxf(rstd, 1e-12f);
        const float Nf = (float)(BS * BS);
        float ma = SA / Nf, ms = (SN + SP) / Nf;
        float rhat = (ma * ma) / fmaxf(ms, 1e-12f);
        float gh2 = gh * gh;
        s_rhn[tid] = rhat * (gh2 * gh + 1.f) * (gh + 1.f) / ((gh2 + 1.f) * (gh2 + 1.f));
    }
    __syncthreads();

    // cooperative brute-force argmin over table (first-index tie-break via key packing)
    float rh[5];
#pragma unroll
    for (int s = 0; s < 5; s++) rh[s] = s_rhn[s];
    unsigned long long best[5];
#pragma unroll
    for (int s = 0; s < 5; s++) best[s] = 0xFFFFFFFFFFFFFFFFull;
    for (int t = tid; t < NTAB; t += NTHR) {
        float rv = g_rg[t];
#pragma unroll
        for (int s = 0; s < 5; s++) {
            float d = fabsf(rv - rh[s]);
            unsigned long long key =
                ((unsigned long long)__float_as_uint(d) << 32) | (unsigned)t;
            best[s] = umin64(best[s], key);
        }
    }
#pragma unroll
    for (int s = 0; s < 5; s++)
#pragma unroll
        for (int off = 16; off > 0; off >>= 1)
            best[s] = umin64(best[s], __shfl_down_sync(0xffffffffu, best[s], off));
    if (lane == 0) {
#pragma unroll
        for (int s = 0; s < 5; s++) s_wmin[warp][s] = best[s];
    }
    __syncthreads();

    if (tid < 5) {
        unsigned long long mb = s_wmin[0][tid];
        for (int wi = 1; wi < NW; wi++) mb = umin64(mb, s_wmin[wi][tid]);
        int idxm = (int)(mb & 0xFFFFFFFFull);
        float alpha = (float)(0.2 + 0.001 * (double)idxm);
        float conv = expf(0.5f * (lgammaf(1.f / alpha) - lgammaf(3.f / alpha)));
        float bl = lstd * conv, br = rstd * conv;
        float* fo = &g_feats[((size_t)b * NBLK + blk) * 36 + foff];
        if (tid == 0) {
            fo[0] = alpha;
            fo[1] = 0.5f * (bl + br);
        } else {
            int o = 2 + (tid - 1) * 4;
            fo[o] = alpha;
            fo[o + 1] = (br - bl) * expf(lgammaf(2.f / alpha) - lgammaf(1.f / alpha));
            fo[o + 2] = bl;
            fo[o + 3] = br;
        }
    }
}

// ---------------- final: mean/cov, Cholesky of (cov_pris+cov_dist)/2, Mahalanobis --
__global__ void final_kernel(const float* __restrict__ mu_pris,
                             const float* __restrict__ cov_pris,
                             float* __restrict__ out) {
    __shared__ float sd[NBLK * 36];
    __shared__ float sM[36 * 36];
    __shared__ float smu[36];
    __shared__ float sdiff[36];
    __shared__ float sz[36];
    int b = blockIdx.x, tid = threadIdx.x;
    const int NT = 128;
    const float* fb = &g_feats[(size_t)b * NBLK * 36];
    for (int i = tid; i < NBLK * 36; i += NT) sd[i] = fb[i];
    __syncthreads();
    if (tid < 36) {
        float s = 0.f;
        for (int n = 0; n < NBLK; n++) s += sd[n * 36 + tid];
        float m = s / 100.0f;
        smu[tid] = m;
        sdiff[tid] = mu_pris[tid] - m;
    }
    __syncthreads();
    for (int idx = tid; idx < 36 * 36; idx += NT) {
        int f = idx / 36, g = idx - f * 36;
        if (g < f) continue;
        float mf = smu[f], mg = smu[g], s = 0.f;
        for (int n = 0; n < NBLK; n++)
            s = fmaf(sd[n * 36 + f] - mf, sd[n * 36 + g] - mg, s);
        s /= 99.0f;
        float m = 0.5f * (cov_pris[idx] + s);
        sM[f * 36 + g] = m;
        sM[g * 36 + f] = m;
    }
    __syncthreads();
    // in-place lower Cholesky (M is SPD: cov_pris has +I, cov_dist PSD)
    for (int j = 0; j < 36; j++) {
        if (tid == 0) {
            float s = sM[j * 36 + j];
            for (int k = 0; k < j; k++) {
                float l = sM[j * 36 + k];
                s -= l * l;
            }
            sM[j * 36 + j] = sqrtf(fmaxf(s, 1e-20f));
        }
        __syncthreads();
        for (int i = j + 1 + tid; i < 36; i += NT) {
            float s = sM[i * 36 + j];
            for (int k = 0; k < j; k++) s -= sM[i * 36 + k] * sM[j * 36 + k];
            sM[i * 36 + j] = s / sM[j * 36 + j];
        }
        __syncthreads();
    }
    // q = ||L^{-1} diff||^2  (forward substitution by warp 0)
    if (tid < 32) {
        for (int i = 0; i < 36; i++) {
            float p = 0.f;
            for (int k = tid; k < i; k += 32) p += sM[i * 36 + k] * sz[k];
#pragma unroll
            for (int off = 16; off > 0; off >>= 1)
                p += __shfl_down_sync(0xffffffffu, p, off);
            if (tid == 0) sz[i] = (sdiff[i] - p) / sM[i * 36 + i];
            __syncwarp();
        }
        if (tid == 0) {
            float q = 0.f;
            for (int i = 0; i < 36; i++) q += sz[i] * sz[i];
            out[b] = sqrtf(fmaxf(q, 0.f));
        }
    }
}

// ---------------- launch -----------------------------------------------------------
extern "C" void kernel_launch(void* const* d_in, const int* in_sizes, int n_in,
                              void* d_out, int out_size) {
    const float* X = (const float*)d_in[0];
    const float* mu_pris = (const float*)d_in[1];
    const float* cov_pris = (const float*)d_in[2];
    float* out = (float*)d_out;

    const size_t sm1 = (size_t)(102 * 102 + 2 * 102 * 96 + 96 * 96) * sizeof(float);
    const size_t sm2 = (size_t)(54 * 54 + 2 * 54 * 48 + 48 * 48) * sizeof(float);
    cudaFuncSetAttribute(feat_kernel<96, 512, false>,
                         cudaFuncAttributeMaxDynamicSharedMemorySize, (int)sm1);
    cudaFuncSetAttribute(feat_kernel<48, 256, true>,
                         cudaFuncAttributeMaxDynamicSharedMemorySize, (int)sm2);

    init_tables_kernel<<<(NTAB + 255) / 256, 256>>>();
    feat_kernel<96, 512, false><<<dim3(NBLK, BATCH), 512, sm1>>>(X, HW1, 0);
    down_kernel<<<dim3((HW2 * HW2 + 255) / 256, BATCH), 256>>>(X);
    feat_kernel<48, 256, true><<<dim3(NBLK, BATCH), 256, sm2>>>(X, HW2, 18);
    final_kernel<<<BATCH, 128>>>(mu_pris, cov_pris, out);
}

// round 2
// speedup vs baseline: 1.2557x; 1.2557x over previous
#include <cuda_runtime.h>
#include <math.h>

#define BATCH 32
#define HW1 960
#define HW2 480
#define NB 10
#define NBLK 100
#define NTAB 9801

// ---------------- device scratch (no allocations allowed) ----------------
__device__ float g_rg[NTAB];                 // AGGD r(gamma) table (monotone increasing)
__device__ float g_w7[7];                    // 1D normalized 7-tap gaussian (sigma 7/6)
__device__ float g_w3[9];                    // 2D normalized 3x3 gaussian (sigma 0.5)
__device__ float g_feats[BATCH * NBLK * 36]; // 36 features per block

// ---------------- table / weight init (deterministic each launch) ----------------
__global__ void init_tables_kernel() {
    int i = blockIdx.x * blockDim.x + threadIdx.x;
    if (i < NTAB) {
        double g = 0.2 + 0.001 * (double)i;
        g_rg[i] = (float)exp(2.0 * lgamma(2.0 / g) - lgamma(1.0 / g) - lgamma(3.0 / g));
    }
    if (i == 0) {
        double e[7], s = 0.0;
        double sig = 7.0 / 6.0;
        for (int j = 0; j < 7; j++) {
            double ax = (double)j - 3.0;
            e[j] = exp(-(ax * ax) / (2.0 * sig * sig));
            s += e[j];
        }
        for (int j = 0; j < 7; j++) g_w7[j] = (float)(e[j] / s);
        double e3[3], s3 = 0.0;
        for (int j = 0; j < 3; j++) {
            double ax = (double)j - 1.0;
            e3[j] = exp(-(ax * ax) / (2.0 * 0.25));
            s3 += e3[j];
        }
        double tot = s3 * s3;
        for (int a = 0; a < 3; a++)
            for (int c = 0; c < 3; c++) g_w3[a * 3 + c] = (float)(e3[a] * e3[c] / tot);
    }
}

// Warp-cooperative argmin over the monotone-increasing table.
// Returns the first index minimizing |g_rg[i] - t| (matches jnp.argmin semantics).
static __device__ __forceinline__ int argmin_table_warp(float t, int lane) {
    int lo = -1, hi = NTAB;  // invariant: A[lo] < t (lo==-1 virtual), A[hi] >= t (hi==NTAB virtual)
    while (hi - lo > 1) {
        int w = hi - lo - 1;
        int pos = lo + 1 + (int)(((unsigned)lane * (unsigned)w) >> 5);
        float v = __ldg(&g_rg[pos]);
        unsigned m = __ballot_sync(0xffffffffu, v < t);
        if (m == 0u) {
            hi = lo + 1;
        } else {
            int last = 31 - __clz(m);
            int nlo = __shfl_sync(0xffffffffu, pos, last);
            int nhi = hi;
            if (m != 0xffffffffu) {
                int first = __ffs(~m) - 1;
                nhi = __shfl_sync(0xffffffffu, pos, first);
            }
            lo = nlo;
            hi = nhi;
        }
    }
    int j = hi;
    if (j <= 0) return 0;
    if (j >= NTAB) return NTAB - 1;
    float d0 = fabsf(__ldg(&g_rg[j - 1]) - t);
    float d1 = fabsf(__ldg(&g_rg[j]) - t);
    return (d0 <= d1) ? (j - 1) : j;  // tie -> lower index (first occurrence)
}

// ---------------- fused per-block: (optional downsample) + MSCN + AGGD features ----
// One CTA per block. FUSE_DOWN: compute the 3x3 sigma=0.5 zero-pad stride-2
// downsample of X on the fly while loading the halo tile.
template <int BS, int NTHR, bool FUSE_DOWN>
__global__ __launch_bounds__(NTHR) void feat_kernel(const float* __restrict__ X,
                                                    int HW, int foff) {
    const int TILE = BS + 6;
    const int NW = NTHR / 32;
    const int KC = (BS + 31) / 32;  // col chunks of 32 lanes
    const int tid = threadIdx.x;
    const int warp = tid >> 5, lane = tid & 31;
    const int blk = blockIdx.x;
    const int b = blockIdx.y;
    const int by0 = (blk / NB) * BS;
    const int bx0 = (blk - (blk / NB) * NB) * BS;

    extern __shared__ float sm[];
    float* T = sm;                 // TILE*TILE tile; center later overwritten by xn
    float* rX = T + TILE * TILE;   // TILE*BS horizontal conv of x
    float* rX2 = rX + TILE * BS;   // TILE*BS horizontal conv of x^2

    __shared__ float s_wsum[NW][25];
    __shared__ float s_tot[25];
    __shared__ float s_rhn[5], s_lstd[5], s_rstd[5];

    float w[7];
#pragma unroll
    for (int j = 0; j < 7; j++) w[j] = g_w7[j];

    // ---- load halo tile (replicate clamp in the working-image domain) ----
    if (FUSE_DOWN) {
        float w3[9];
#pragma unroll
        for (int k = 0; k < 9; k++) w3[k] = g_w3[k];
        const float* im = X + (size_t)b * HW1 * HW1;
        for (int idx = tid; idx < TILE * TILE; idx += NTHR) {
            int r = idx / TILE, c = idx - r * TILE;
            int gy = by0 + r - 3;
            gy = gy < 0 ? 0 : (gy >= HW ? HW - 1 : gy);
            int gx = bx0 + c - 3;
            gx = gx < 0 ? 0 : (gx >= HW ? HW - 1 : gx);
            float s = 0.f;
#pragma unroll
            for (int di = 0; di < 3; di++) {
                int sy = 2 * gy + di - 1;
                if (sy < 0 || sy >= HW1) continue;
#pragma unroll
                for (int dj = 0; dj < 3; dj++) {
                    int sx = 2 * gx + dj - 1;
                    if (sx < 0 || sx >= HW1) continue;
                    s = fmaf(w3[di * 3 + dj], __ldg(&im[(size_t)sy * HW1 + sx]), s);
                }
            }
            T[idx] = s;
        }
    } else {
        const float* im = X + (size_t)b * HW * HW;
        for (int idx = tid; idx < TILE * TILE; idx += NTHR) {
            int r = idx / TILE, c = idx - r * TILE;
            int gy = by0 + r - 3;
            gy = gy < 0 ? 0 : (gy >= HW ? HW - 1 : gy);
            int gx = bx0 + c - 3;
            gx = gx < 0 ? 0 : (gx >= HW ? HW - 1 : gx);
            T[idx] = __ldg(&im[(size_t)gy * HW + gx]);
        }
    }
    __syncthreads();

    // ---- separable 7-tap, horizontal pass for x and x^2 ----
    for (int r = warp; r < TILE; r += NW) {
        const float* tr = &T[r * TILE];
#pragma unroll
        for (int k = 0; k < KC; k++) {
            int c = lane + 32 * k;
            if (KC * 32 != BS && c >= BS) continue;
            float a1 = 0.f, a2 = 0.f;
#pragma unroll
            for (int j = 0; j < 7; j++) {
                float v = tr[c + j];
                a1 = fmaf(w[j], v, a1);
                a2 = fmaf(w[j] * v, v, a2);
            }
            rX[r * BS + c] = a1;
            rX2[r * BS + c] = a2;
        }
    }
    __syncthreads();

    // ---- vertical pass + MSCN; write xn in-place into T center ----
    for (int r = warp; r < BS; r += NW) {
#pragma unroll
        for (int k = 0; k < KC; k++) {
            int c = lane + 32 * k;
            if (KC * 32 != BS && c >= BS) continue;
            float mu = 0.f, e2 = 0.f;
#pragma unroll
            for (int i2 = 0; i2 < 7; i2++) {
                mu = fmaf(w[i2], rX[(r + i2) * BS + c], mu);
                e2 = fmaf(w[i2], rX2[(r + i2) * BS + c], e2);
            }
            float sig = sqrtf(fabsf(e2 - mu * mu));
            int center = (r + 3) * TILE + (c + 3);
            T[center] = (T[center] - mu) / (sig + 1.0f);  // only this thread touches it
        }
    }
    __syncthreads();

    // ---- AGGD stats of 5 signals (block + 4 circular-shifted products) ----
    float acc[25];
#pragma unroll
    for (int k = 0; k < 25; k++) acc[k] = 0.f;
    for (int r = warp; r < BS; r += NW) {
        int rm = (r == 0) ? (BS - 1) : (r - 1);
        const float* rowC = &T[(r + 3) * TILE + 3];
        const float* rowM = &T[(rm + 3) * TILE + 3];
#pragma unroll
        for (int k = 0; k < KC; k++) {
            int c = lane + 32 * k;
            if (KC * 32 != BS && c >= BS) continue;
            int cm = (c == 0) ? (BS - 1) : (c - 1);
            int cp = (c == BS - 1) ? 0 : (c + 1);
            float x0 = rowC[c];
            float y[5];
            y[0] = x0;
            y[1] = x0 * rowC[cm];   // shift (0,1)
            y[2] = x0 * rowM[c];    // shift (1,0)
            y[3] = x0 * rowM[cm];   // shift (1,1)
            y[4] = x0 * rowM[cp];   // shift (1,-1)
#pragma unroll
            for (int s = 0; s < 5; s++) {
                float v = y[s], v2 = v * v;
                float neg = (v < 0.f) ? 1.f : 0.f;
                float pos = (v > 0.f) ? 1.f : 0.f;
                acc[s * 5 + 0] += v2 * neg;
                acc[s * 5 + 1] += v2 * pos;
                acc[s * 5 + 2] += neg;
                acc[s * 5 + 3] += pos;
                acc[s * 5 + 4] += fabsf(v);
            }
        }
    }
#pragma unroll
    for (int k = 0; k < 25; k++)
#pragma unroll
        for (int off = 16; off > 0; off >>= 1)
            acc[k] += __shfl_down_sync(0xffffffffu, acc[k], off);
    if (lane == 0) {
#pragma unroll
        for (int k = 0; k < 25; k++) s_wsum[warp][k] = acc[k];
    }
    __syncthreads();
    if (tid < 25) {
        float s = 0.f;
        for (int wi = 0; wi < NW; wi++) s += s_wsum[wi][tid];
        s_tot[tid] = s;
    }
    __syncthreads();

    if (tid < 5) {
        float SN = s_tot[tid * 5 + 0], SP = s_tot[tid * 5 + 1];
        float CN = s_tot[tid * 5 + 2], CP = s_tot[tid * 5 + 3];
        float SA = s_tot[tid * 5 + 4];
        float cl = fmaxf(CN, 1.f), cr = fmaxf(CP, 1.f);
        float lstd = sqrtf(SN / cl);
        float rstd = sqrtf(SP / cr);
        s_lstd[tid] = lstd;
        s_rstd[tid] = rstd;
        float gh = lstd / fmaxf(rstd, 1e-12f);
        const float Nf = (float)(BS * BS);
        float ma = SA / Nf, ms = (SN + SP) / Nf;
        float rhat = (ma * ma) / fmaxf(ms, 1e-12f);
        float gh2 = gh * gh;
        s_rhn[tid] = rhat * (gh2 * gh + 1.f) * (gh + 1.f) / ((gh2 + 1.f) * (gh2 + 1.f));
    }
    __syncthreads();

    // ---- warps 0..4: table inversion via warp 32-ary search (monotone table) ----
    if (warp < 5) {
        int idxm = argmin_table_warp(s_rhn[warp], lane);
        if (lane == 0) {
            float alpha = (float)(0.2 + 0.001 * (double)idxm);
            float conv = expf(0.5f * (lgammaf(1.f / alpha) - lgammaf(3.f / alpha)));
            float bl = s_lstd[warp] * conv, br = s_rstd[warp] * conv;
            float* fo = &g_feats[((size_t)b * NBLK + blk) * 36 + foff];
            if (warp == 0) {
                fo[0] = alpha;
                fo[1] = 0.5f * (bl + br);
            } else {
                int o = 2 + (warp - 1) * 4;
                fo[o] = alpha;
                fo[o + 1] = (br - bl) * expf(lgammaf(2.f / alpha) - lgammaf(1.f / alpha));
                fo[o + 2] = bl;
                fo[o + 3] = br;
            }
        }
    }
}

// ---------------- final: mean/cov, Cholesky of (cov_pris+cov_dist)/2, Mahalanobis --
__global__ void final_kernel(const float* __restrict__ mu_pris,
                             const float* __restrict__ cov_pris,
                             float* __restrict__ out) {
    __shared__ float sd[NBLK * 36];
    __shared__ float sM[36 * 36];
    __shared__ float smu[36];
    __shared__ float sdiff[36];
    __shared__ float sz[36];
    int b = blockIdx.x, tid = threadIdx.x;
    const int NT = 128;
    const float* fb = &g_feats[(size_t)b * NBLK * 36];
    for (int i = tid; i < NBLK * 36; i += NT) sd[i] = fb[i];
    __syncthreads();
    if (tid < 36) {
        float s = 0.f;
        for (int n = 0; n < NBLK; n++) s += sd[n * 36 + tid];
        float m = s / 100.0f;
        smu[tid] = m;
        sdiff[tid] = mu_pris[tid] - m;
    }
    __syncthreads();
    for (int idx = tid; idx < 36 * 36; idx += NT) {
        int f = idx / 36, g = idx - f * 36;
        if (g < f) continue;
        float mf = smu[f], mg = smu[g], s = 0.f;
        for (int n = 0; n < NBLK; n++)
            s = fmaf(sd[n * 36 + f] - mf, sd[n * 36 + g] - mg, s);
        s /= 99.0f;
        float m = 0.5f * (cov_pris[idx] + s);
        sM[f * 36 + g] = m;
        sM[g * 36 + f] = m;
    }
    __syncthreads();
    // in-place lower Cholesky (M is SPD: cov_pris has +I, cov_dist PSD)
    for (int j = 0; j < 36; j++) {
        if (tid == 0) {
            float s = sM[j * 36 + j];
            for (int k = 0; k < j; k++) {
                float l = sM[j * 36 + k];
                s -= l * l;
            }
            sM[j * 36 + j] = sqrtf(fmaxf(s, 1e-20f));
        }
        __syncthreads();
        for (int i = j + 1 + tid; i < 36; i += NT) {
            float s = sM[i * 36 + j];
            for (int k = 0; k < j; k++) s -= sM[i * 36 + k] * sM[j * 36 + k];
            sM[i * 36 + j] = s / sM[j * 36 + j];
        }
        __syncthreads();
    }
    // q = ||L^{-1} diff||^2 (forward substitution by warp 0)
    if (tid < 32) {
        for (int i = 0; i < 36; i++) {
            float p = 0.f;
            for (int k = tid; k < i; k += 32) p += sM[i * 36 + k] * sz[k];
#pragma unroll
            for (int off = 16; off > 0; off >>= 1)
                p += __shfl_down_sync(0xffffffffu, p, off);
            if (tid == 0) sz[i] = (sdiff[i] - p) / sM[i * 36 + i];
            __syncwarp();
        }
        if (tid == 0) {
            float q = 0.f;
            for (int i = 0; i < 36; i++) q += sz[i] * sz[i];
            out[b] = sqrtf(fmaxf(q, 0.f));
        }
    }
}

// ---------------- launch -----------------------------------------------------------
extern "C" void kernel_launch(void* const* d_in, const int* in_sizes, int n_in,
                              void* d_out, int out_size) {
    const float* X = (const float*)d_in[0];
    const float* mu_pris = (const float*)d_in[1];
    const float* cov_pris = (const float*)d_in[2];
    float* out = (float*)d_out;

    const size_t sm1 = (size_t)(102 * 102 + 2 * 102 * 96) * sizeof(float);
    const size_t sm2 = (size_t)(54 * 54 + 2 * 54 * 48) * sizeof(float);
    cudaFuncSetAttribute(feat_kernel<96, 1024, false>,
                         cudaFuncAttributeMaxDynamicSharedMemorySize, (int)sm1);
    cudaFuncSetAttribute(feat_kernel<48, 256, true>,
                         cudaFuncAttributeMaxDynamicSharedMemorySize, (int)sm2);

    init_tables_kernel<<<(NTAB + 255) / 256, 256>>>();
    feat_kernel<96, 1024, false><<<dim3(NBLK, BATCH), 1024, sm1>>>(X, HW1, 0);
    feat_kernel<48, 256, true><<<dim3(NBLK, BATCH), 256, sm2>>>(X, HW2, 18);
    final_kernel<<<BATCH, 128>>>(mu_pris, cov_pris, out);
}

// round 3
// speedup vs baseline: 1.6066x; 1.2795x over previous
#include <cuda_runtime.h>
#include <math.h>

#define BATCH 32
#define HW1 960
#define NTAB 9801
#define NTHR 576
#define NW 18

// ---------------- device scratch ----------------
__device__ float g_rg[NTAB];                  // AGGD r(gamma) table (monotone increasing)
__device__ float g_w7[7];                     // 7-tap gaussian, sigma 7/6
__device__ float g_w3[9];                     // 3x3 gaussian, sigma 0.5
__device__ float g_feats[BATCH * 100 * 36];

static __device__ __forceinline__ float fsqrt_ap(float x) {
    float r; asm("sqrt.approx.f32 %0, %1;" : "=f"(r) : "f"(x)); return r;
}
static __device__ __forceinline__ float fdiv_ap(float a, float b) {
    float r; asm("div.approx.f32 %0, %1, %2;" : "=f"(r) : "f"(a), "f"(b)); return r;
}

// ---------------- init (float table; double only for weights) ----------------
__global__ void init_tables_kernel() {
    int i = blockIdx.x * blockDim.x + threadIdx.x;
    if (i < NTAB) {
        double g = 0.2 + 0.001 * (double)i;
        float a1 = (float)(1.0 / g), a2 = (float)(2.0 / g), a3 = (float)(3.0 / g);
        g_rg[i] = expf(2.f * lgammaf(a2) - lgammaf(a1) - lgammaf(a3));
    }
    if (i == 0) {
        double e[7], s = 0.0, sig = 7.0 / 6.0;
        for (int j = 0; j < 7; j++) {
            double ax = (double)j - 3.0;
            e[j] = exp(-(ax * ax) / (2.0 * sig * sig));
            s += e[j];
        }
        for (int j = 0; j < 7; j++) g_w7[j] = (float)(e[j] / s);
        double e3[3], s3 = 0.0;
        for (int j = 0; j < 3; j++) {
            double ax = (double)j - 1.0;
            e3[j] = exp(-(ax * ax) / 0.5);
            s3 += e3[j];
        }
        double tot = s3 * s3;
        for (int a = 0; a < 3; a++)
            for (int c = 0; c < 3; c++) g_w3[a * 3 + c] = (float)(e3[a] * e3[c] / tot);
    }
}

// Warp-cooperative argmin over monotone table; first-index tie-break.
static __device__ __forceinline__ int argmin_table_warp(float t, int lane) {
    int lo = -1, hi = NTAB;
    while (hi - lo > 1) {
        int w = hi - lo - 1;
        int pos = lo + 1 + (int)(((unsigned)lane * (unsigned)w) >> 5);
        float v = __ldg(&g_rg[pos]);
        unsigned m = __ballot_sync(0xffffffffu, v < t);
        if (m == 0u) {
            hi = lo + 1;
        } else {
            int last = 31 - __clz(m);
            int nlo = __shfl_sync(0xffffffffu, pos, last);
            int nhi = hi;
            if (m != 0xffffffffu) {
                int first = __ffs(~m) - 1;
                nhi = __shfl_sync(0xffffffffu, pos, first);
            }
            lo = nlo; hi = nhi;
        }
    }
    int j = hi;
    if (j <= 0) return 0;
    if (j >= NTAB) return NTAB - 1;
    float d0 = fabsf(__ldg(&g_rg[j - 1]) - t);
    float d1 = fabsf(__ldg(&g_rg[j]) - t);
    return (d0 <= d1) ? (j - 1) : j;
}

// ---------------- AGGD stats + features from an xn block in smem ----------------
static __device__ __forceinline__ void aggd_features(
    const float* xnb, int stride, int BS, float Nf, int b, int blk, int foff,
    int tid, float (*s_wsum)[20], float* s_tot, float* s_par) {
    int warp = tid >> 5, lane = tid & 31;
    float acc[20];
#pragma unroll
    for (int k = 0; k < 20; k++) acc[k] = 0.f;
    for (int r = warp; r < BS; r += NW) {
        int rm = (r == 0) ? (BS - 1) : (r - 1);
        const float* rowC = xnb + r * stride;
        const float* rowM = xnb + rm * stride;
        for (int c = lane; c < BS; c += 32) {
            int cm = (c == 0) ? (BS - 1) : (c - 1);
            int cp = (c == BS - 1) ? 0 : (c + 1);
            float x0 = rowC[c];
            float y[5];
            y[0] = x0;
            y[1] = x0 * rowC[cm];
            y[2] = x0 * rowM[c];
            y[3] = x0 * rowM[cm];
            y[4] = x0 * rowM[cp];
#pragma unroll
            for (int s = 0; s < 5; s++) {
                float v = y[s], v2 = v * v;
                acc[s * 4 + 0] += v2;                     // S2
                if (v > 0.f) { acc[s * 4 + 1] += v2;      // SP2
                               acc[s * 4 + 2] += 1.f; }   // CP
                acc[s * 4 + 3] += fabsf(v);               // SA
            }
        }
    }
#pragma unroll
    for (int k = 0; k < 20; k++)
#pragma unroll
        for (int off = 16; off > 0; off >>= 1)
            acc[k] += __shfl_down_sync(0xffffffffu, acc[k], off);
    if (lane == 0) {
#pragma unroll
        for (int k = 0; k < 20; k++) s_wsum[warp][k] = acc[k];
    }
    __syncthreads();
    if (tid < 20) {
        float s = 0.f;
        for (int wi = 0; wi < NW; wi++) s += s_wsum[wi][tid];
        s_tot[tid] = s;
    }
    __syncthreads();
    if (tid < 5) {
        float S2 = s_tot[tid * 4 + 0], SP2 = s_tot[tid * 4 + 1];
        float CP = s_tot[tid * 4 + 2], SA = s_tot[tid * 4 + 3];
        float SN2 = fmaxf(S2 - SP2, 0.f);
        float CN = Nf - CP;
        float lstd = sqrtf(SN2 / fmaxf(CN, 1.f));
        float rstd = sqrtf(SP2 / fmaxf(CP, 1.f));
        s_par[5 + tid] = lstd;
        s_par[10 + tid] = rstd;
        float gh = lstd / fmaxf(rstd, 1e-12f);
        float ma = SA / Nf, ms = S2 / Nf;
        float rhat = (ma * ma) / fmaxf(ms, 1e-12f);
        float gh2 = gh * gh;
        s_par[tid] = rhat * (gh2 * gh + 1.f) * (gh + 1.f) / ((gh2 + 1.f) * (gh2 + 1.f));
    }
    __syncthreads();
    if (warp < 5) {
        int idxm = argmin_table_warp(s_par[warp], lane);
        if (lane == 0) {
            float alpha = (float)(0.2 + 0.001 * (double)idxm);
            float conv = expf(0.5f * (lgammaf(1.f / alpha) - lgammaf(3.f / alpha)));
            float bl = s_par[5 + warp] * conv, br = s_par[10 + warp] * conv;
            float* fo = &g_feats[((size_t)b * 100 + blk) * 36 + foff];
            if (warp == 0) {
                fo[0] = alpha;
                fo[1] = 0.5f * (bl + br);
            } else {
                int o = 2 + (warp - 1) * 4;
                fo[o] = alpha;
                fo[o + 1] = (br - bl) * expf(lgammaf(2.f / alpha) - lgammaf(1.f / alpha));
                fo[o + 2] = bl;
                fo[o + 3] = br;
            }
        }
    }
}

// ---------------- unified feature kernel: blocks 0..3199 scale1, 3200..6399 scale2 --
__global__ __launch_bounds__(NTHR, 2) void feat_kernel(const float* __restrict__ X) {
    extern __shared__ float sm[];
    __shared__ float s_wsum[NW][20];
    __shared__ float s_tot[20];
    __shared__ float s_par[15];
    int tid = threadIdx.x, warp = tid >> 5, lane = tid & 31;
    float w[7];
#pragma unroll
    for (int j = 0; j < 7; j++) w[j] = g_w7[j];
    int id = blockIdx.x;

    if (id < 3200) {
        // -------- scale 1: 96x96 block, rolling-register vertical conv --------
        int b = id / 100, blk = id - 100 * b;
        int by0 = (blk / 10) * 96, bx0 = (blk % 10) * 96;
        float* T = sm;               // 102x102
        float* xn = sm + 102 * 102;  // 96x96
        const float* im = X + (size_t)b * HW1 * HW1;
        for (int idx = tid; idx < 102 * 102; idx += NTHR) {
            int r = idx / 102, c = idx - r * 102;
            int gy = by0 + r - 3; gy = gy < 0 ? 0 : (gy > 959 ? 959 : gy);
            int gx = bx0 + c - 3; gx = gx < 0 ? 0 : (gx > 959 ? 959 : gx);
            T[idx] = __ldg(&im[gy * HW1 + gx]);
        }
        __syncthreads();

        int seg = warp / 3, strip = warp - seg * 3;
        int c = strip * 32 + lane;       // 0..95
        int r0 = seg * 16;               // output rows r0..r0+15
        float w1[7], w2[7];
#pragma unroll
        for (int j = 0; j < 22; j++) {
            const float* row = &T[(r0 + j) * 102 + c];
            float a1 = 0.f, a2 = 0.f;
#pragma unroll
            for (int t = 0; t < 7; t++) {
                float v = row[t];
                a1 = fmaf(w[t], v, a1);
                a2 = fmaf(w[t], v * v, a2);
            }
            w1[j % 7] = a1; w2[j % 7] = a2;
            if (j >= 6) {
                int r = r0 + j - 6;
                float mu = 0.f, e2 = 0.f;
#pragma unroll
                for (int i = 0; i < 7; i++) {
                    mu = fmaf(w[i], w1[(j - 6 + i) % 7], mu);
                    e2 = fmaf(w[i], w2[(j - 6 + i) % 7], e2);
                }
                float v = fmaxf(fabsf(e2 - mu * mu), 1e-30f);
                float sig = fsqrt_ap(v);
                float x = T[(r + 3) * 102 + c + 3];
                xn[r * 96 + c] = fdiv_ap(x - mu, sig + 1.f);
            }
        }
        __syncthreads();
        aggd_features(xn, 96, 96, 9216.f, b, blk, 0, tid, s_wsum, s_tot, s_par);
    } else {
        // -------- scale 2: stage X region, fused downsample, 48x48 block --------
        int id2 = id - 3200;
        int b = id2 / 100, blk = id2 - 100 * b;
        int by0 = (blk / 10) * 48, bx0 = (blk % 10) * 48;
        float* S = sm;                   // 109 x 109 staged (stride 112)
        float* T = S + 109 * 112;        // 54x54 downsampled tile; center becomes xn
        float* rX = T + 54 * 54;         // 54x48
        float* rX2 = rX + 54 * 48;       // 54x48
        const float* im = X + (size_t)b * HW1 * HW1;
        int sy0 = 2 * by0 - 7, sx0 = 2 * bx0 - 7;
        for (int idx = tid; idx < 109 * 109; idx += NTHR) {
            int i = idx / 109, cc = idx - 109 * i;
            int gr = sy0 + i, gc = sx0 + cc;
            float v = 0.f;
            if (gr >= 0 && gr < 960 && gc >= 0 && gc < 960) v = __ldg(&im[gr * HW1 + gc]);
            S[i * 112 + cc] = v;
        }
        float w3[9];
#pragma unroll
        for (int k = 0; k < 9; k++) w3[k] = g_w3[k];
        __syncthreads();
        for (int idx = tid; idx < 54 * 54; idx += NTHR) {
            int r = idx / 54, cc = idx - 54 * r;
            int gy = by0 + r - 3; gy = gy < 0 ? 0 : (gy > 479 ? 479 : gy);
            int gx = bx0 + cc - 3; gx = gx < 0 ? 0 : (gx > 479 ? 479 : gx);
            const float* p = &S[(2 * gy - 1 - sy0) * 112 + (2 * gx - 1 - sx0)];
            float s = 0.f;
#pragma unroll
            for (int di = 0; di < 3; di++)
#pragma unroll
                for (int dj = 0; dj < 3; dj++)
                    s = fmaf(w3[di * 3 + dj], p[di * 112 + dj], s);
            T[idx] = s;
        }
        __syncthreads();
        for (int idx = tid; idx < 54 * 48; idx += NTHR) {
            int r = idx / 48, cc = idx - 48 * r;
            const float* tr = &T[r * 54 + cc];
            float a1 = 0.f, a2 = 0.f;
#pragma unroll
            for (int t = 0; t < 7; t++) {
                float v = tr[t];
                a1 = fmaf(w[t], v, a1);
                a2 = fmaf(w[t], v * v, a2);
            }
            rX[idx] = a1; rX2[idx] = a2;
        }
        __syncthreads();
        for (int idx = tid; idx < 48 * 48; idx += NTHR) {
            int r = idx / 48, cc = idx - 48 * r;
            float mu = 0.f, e2 = 0.f;
#pragma unroll
            for (int i = 0; i < 7; i++) {
                mu = fmaf(w[i], rX[(r + i) * 48 + cc], mu);
                e2 = fmaf(w[i], rX2[(r + i) * 48 + cc], e2);
            }
            float v = fmaxf(fabsf(e2 - mu * mu), 1e-30f);
            float sig = fsqrt_ap(v);
            int ctr = (r + 3) * 54 + cc + 3;
            T[ctr] = fdiv_ap(T[ctr] - mu, sig + 1.f);  // in-place xn (owner-only)
        }
        __syncthreads();
        aggd_features(&T[3 * 54 + 3], 54, 48, 2304.f, b, blk, 18, tid, s_wsum, s_tot, s_par);
    }
}

// ---------------- final: mean/cov, Cholesky + fused forward solve ----------------
__global__ __launch_bounds__(256) void final_kernel(const float* __restrict__ mu_pris,
                                                    const float* __restrict__ cov_pris,
                                                    float* __restrict__ out) {
    __shared__ float sd[100 * 36];
    __shared__ float sM[36 * 37];
    __shared__ float smu[36], sdiff[36], sz[36];
    int b = blockIdx.x, tid = threadIdx.x;
    const int NT = 256;
    const float* fb = &g_feats[(size_t)b * 100 * 36];
    for (int i = tid; i < 3600; i += NT) sd[i] = fb[i];
    __syncthreads();
    if (tid < 36) {
        float s = 0.f;
        for (int n = 0; n < 100; n++) s += sd[n * 36 + tid];
        float m = s / 100.0f;
        smu[tid] = m;
        sdiff[tid] = mu_pris[tid] - m;
    }
    __syncthreads();
    for (int idx = tid; idx < 1296; idx += NT) {
        int f = idx / 36, g = idx - f * 36;
        if (g < f) continue;
        float mf = smu[f], mg = smu[g];
        float a0 = 0.f, a1 = 0.f, a2 = 0.f, a3 = 0.f;
        for (int n = 0; n < 100; n += 4) {
            a0 = fmaf(sd[n * 36 + f] - mf, sd[n * 36 + g] - mg, a0);
            a1 = fmaf(sd[(n + 1) * 36 + f] - mf, sd[(n + 1) * 36 + g] - mg, a1);
            a2 = fmaf(sd[(n + 2) * 36 + f] - mf, sd[(n + 2) * 36 + g] - mg, a2);
            a3 = fmaf(sd[(n + 3) * 36 + f] - mf, sd[(n + 3) * 36 + g] - mg, a3);
        }
        float s = ((a0 + a1) + (a2 + a3)) / 99.0f;
        float m = 0.5f * (cov_pris[idx] + s);
        sM[f * 37 + g] = m;
        sM[g * 37 + f] = m;
    }
    __syncthreads();
    // Cholesky with fused forward-substitution: z = L^{-1} diff
    for (int j = 0; j < 36; j++) {
        if (tid < 32) {
            float pd = 0.f, pz = 0.f;
            for (int k = tid; k < j; k += 32) {
                float l = sM[j * 37 + k];
                pd = fmaf(l, l, pd);
                pz = fmaf(l, sz[k], pz);
            }
#pragma unroll
            for (int off = 16; off > 0; off >>= 1) {
                pd += __shfl_down_sync(0xffffffffu, pd, off);
                pz += __shfl_down_sync(0xffffffffu, pz, off);
            }
            if (tid == 0) {
                float d = sqrtf(fmaxf(sM[j * 37 + j] - pd, 1e-20f));
                sM[j * 37 + j] = d;
                sz[j] = (sdiff[j] - pz) / d;
            }
        }
        __syncthreads();
        float dj = sM[j * 37 + j];
        for (int i = j + 1 + tid; i < 36; i += NT) {
            float s = sM[i * 37 + j];
            for (int k = 0; k < j; k++) s -= sM[i * 37 + k] * sM[j * 37 + k];
            sM[i * 37 + j] = s / dj;
        }
        __syncthreads();
    }
    if (tid == 0) {
        float q = 0.f;
        for (int i = 0; i < 36; i++) q += sz[i] * sz[i];
        out[b] = sqrtf(fmaxf(q, 0.f));
    }
}

// ---------------- launch ----------------
extern "C" void kernel_launch(void* const* d_in, const int* in_sizes, int n_in,
                              void* d_out, int out_size) {
    (void)in_sizes; (void)n_in; (void)out_size;
    const float* X = (const float*)d_in[0];
    const float* mu_pris = (const float*)d_in[1];
    const float* cov_pris = (const float*)d_in[2];
    float* out = (float*)d_out;

    const size_t smB = (size_t)(109 * 112 + 54 * 54 + 2 * 54 * 48) * sizeof(float);
    cudaFuncSetAttribute(feat_kernel, cudaFuncAttributeMaxDynamicSharedMemorySize, (int)smB);

    init_tables_kernel<<<(NTAB + 255) / 256, 256>>>();
    feat_kernel<<<6400, NTHR, smB>>>(X);
    final_kernel<<<BATCH, 256>>>(mu_pris, cov_pris, out);
}

// round 4
// speedup vs baseline: 1.8840x; 1.1726x over previous
#include <cuda_runtime.h>
#include <math.h>

#define BATCH 32
#define HW1 960
#define NTAB 9801
#define NTHR 576
#define NW 18

// ---------------- device scratch ----------------
__device__ float g_rg[NTAB];   // AGGD r(gamma) table (monotone increasing)
__device__ float g_w7[7];      // 7-tap gaussian, sigma 7/6 (normalized)
__device__ float g_w3[3];      // 3-tap gaussian, sigma 0.5 (normalized, separable)
__device__ float g_feats[BATCH * 100 * 36];

static __device__ __forceinline__ float fsqrt_ap(float x) {
    float r; asm("sqrt.approx.f32 %0, %1;" : "=f"(r) : "f"(x)); return r;
}
static __device__ __forceinline__ float fdiv_ap(float a, float b) {
    float r; asm("div.approx.f32 %0, %1, %2;" : "=f"(r) : "f"(a), "f"(b)); return r;
}

// ---------------- init ----------------
__global__ void init_tables_kernel() {
    int i = blockIdx.x * blockDim.x + threadIdx.x;
    if (i < NTAB) {
        double g = 0.2 + 0.001 * (double)i;
        float a1 = (float)(1.0 / g), a2 = (float)(2.0 / g), a3 = (float)(3.0 / g);
        g_rg[i] = expf(2.f * lgammaf(a2) - lgammaf(a1) - lgammaf(a3));
    }
    if (i == 0) {
        double e[7], s = 0.0, sig = 7.0 / 6.0;
        for (int j = 0; j < 7; j++) {
            double ax = (double)j - 3.0;
            e[j] = exp(-(ax * ax) / (2.0 * sig * sig));
            s += e[j];
        }
        for (int j = 0; j < 7; j++) g_w7[j] = (float)(e[j] / s);
        double e3[3], s3 = 0.0;
        for (int j = 0; j < 3; j++) {
            double ax = (double)j - 1.0;
            e3[j] = exp(-(ax * ax) / 0.5);
            s3 += e3[j];
        }
        for (int j = 0; j < 3; j++) g_w3[j] = (float)(e3[j] / s3);
    }
}

// Warp-cooperative argmin over monotone table; first-index tie-break.
static __device__ __forceinline__ int argmin_table_warp(float t, int lane) {
    int lo = -1, hi = NTAB;
    while (hi - lo > 1) {
        int w = hi - lo - 1;
        int pos = lo + 1 + (int)(((unsigned)lane * (unsigned)w) >> 5);
        float v = __ldg(&g_rg[pos]);
        unsigned m = __ballot_sync(0xffffffffu, v < t);
        if (m == 0u) {
            hi = lo + 1;
        } else {
            int last = 31 - __clz(m);
            int nlo = __shfl_sync(0xffffffffu, pos, last);
            int nhi = hi;
            if (m != 0xffffffffu) {
                int first = __ffs(~m) - 1;
                nhi = __shfl_sync(0xffffffffu, pos, first);
            }
            lo = nlo; hi = nhi;
        }
    }
    int j = hi;
    if (j <= 0) return 0;
    if (j >= NTAB) return NTAB - 1;
    float d0 = fabsf(__ldg(&g_rg[j - 1]) - t);
    float d1 = fabsf(__ldg(&g_rg[j]) - t);
    return (d0 <= d1) ? (j - 1) : j;
}

// ---------------- AGGD stats + features from an xn block in smem ----------------
// Accumulates S2, SV=sum v|v|, SA per signal (fp, shuffle-reduced) and CP via
// ballot+popc (warp-uniform, lane0 only).
static __device__ __forceinline__ void aggd_features(
    const float* xnb, int stride, int BS, float Nf, int b, int blk, int foff,
    int tid, float (*s_wsum)[20], float* s_tot, float* s_par) {
    int warp = tid >> 5, lane = tid & 31;
    float accf[15];
#pragma unroll
    for (int k = 0; k < 15; k++) accf[k] = 0.f;
    int cp[5];
#pragma unroll
    for (int k = 0; k < 5; k++) cp[k] = 0;
    for (int r = warp; r < BS; r += NW) {
        int rm = (r == 0) ? (BS - 1) : (r - 1);
        const float* rowC = xnb + r * stride;
        const float* rowM = xnb + rm * stride;
        for (int c0 = 0; c0 < BS; c0 += 32) {
            int c = c0 + lane;
            bool act = (c < BS);
            int cs = act ? c : 0;
            int cm = (cs == 0) ? (BS - 1) : (cs - 1);
            int cpn = (cs == BS - 1) ? 0 : (cs + 1);
            float x0 = act ? rowC[cs] : 0.f;
            float y[5];
            y[0] = x0;
            y[1] = x0 * rowC[cm];
            y[2] = x0 * rowM[cs];
            y[3] = x0 * rowM[cm];
            y[4] = x0 * rowM[cpn];
#pragma unroll
            for (int s = 0; s < 5; s++) {
                float v = y[s];
                float fa = fabsf(v);
                accf[s * 3 + 0] = fmaf(v, v, accf[s * 3 + 0]);   // S2
                accf[s * 3 + 1] = fmaf(v, fa, accf[s * 3 + 1]);  // SV
                accf[s * 3 + 2] += fa;                            // SA
                unsigned bal = __ballot_sync(0xffffffffu, v > 0.f);
                cp[s] += __popc(bal);
            }
        }
    }
#pragma unroll
    for (int k = 0; k < 15; k++)
#pragma unroll
        for (int off = 16; off > 0; off >>= 1)
            accf[k] += __shfl_down_sync(0xffffffffu, accf[k], off);
    if (lane == 0) {
#pragma unroll
        for (int k = 0; k < 15; k++) s_wsum[warp][k] = accf[k];
#pragma unroll
        for (int s = 0; s < 5; s++) s_wsum[warp][15 + s] = (float)cp[s];
    }
    __syncthreads();
    if (tid < 20) {
        float s = 0.f;
        for (int wi = 0; wi < NW; wi++) s += s_wsum[wi][tid];
        s_tot[tid] = s;
    }
    __syncthreads();
    if (tid < 5) {
        float S2 = s_tot[tid * 3 + 0], SV = s_tot[tid * 3 + 1], SA = s_tot[tid * 3 + 2];
        float CP = s_tot[15 + tid];
        float SP2 = 0.5f * (S2 + SV);
        float SN2 = fmaxf(0.5f * (S2 - SV), 0.f);
        float CN = Nf - CP;
        float lstd = sqrtf(SN2 / fmaxf(CN, 1.f));
        float rstd = sqrtf(SP2 / fmaxf(CP, 1.f));
        s_par[5 + tid] = lstd;
        s_par[10 + tid] = rstd;
        float gh = lstd / fmaxf(rstd, 1e-12f);
        float ma = SA / Nf, ms = S2 / Nf;
        float rhat = (ma * ma) / fmaxf(ms, 1e-12f);
        float gh2 = gh * gh;
        s_par[tid] = rhat * (gh2 * gh + 1.f) * (gh + 1.f) / ((gh2 + 1.f) * (gh2 + 1.f));
    }
    __syncthreads();
    if (warp < 5) {
        int idxm = argmin_table_warp(s_par[warp], lane);
        if (lane == 0) {
            float alpha = (float)(0.2 + 0.001 * (double)idxm);
            float conv = expf(0.5f * (lgammaf(1.f / alpha) - lgammaf(3.f / alpha)));
            float bl = s_par[5 + warp] * conv, br = s_par[10 + warp] * conv;
            float* fo = &g_feats[((size_t)b * 100 + blk) * 36 + foff];
            if (warp == 0) {
                fo[0] = alpha;
                fo[1] = 0.5f * (bl + br);
            } else {
                int o = 2 + (warp - 1) * 4;
                fo[o] = alpha;
                fo[o + 1] = (br - bl) * expf(lgammaf(2.f / alpha) - lgammaf(1.f / alpha));
                fo[o + 2] = bl;
                fo[o + 3] = br;
            }
        }
    }
}

// ---------------- unified feature kernel ----------------
// ids 0..3199: scale 1 (96x96 blocks, two 48-row phases)
// ids 3200..6399: scale 2 (separable fused downsample + 48x48 blocks)
__global__ __launch_bounds__(NTHR, 3) void feat_kernel(const float* __restrict__ X) {
    extern __shared__ float sm[];
    __shared__ float s_wsum[NW][20];
    __shared__ float s_tot[20];
    __shared__ float s_par[15];
    int tid = threadIdx.x, warp = tid >> 5, lane = tid & 31;
    float w[7];
#pragma unroll
    for (int j = 0; j < 7; j++) w[j] = g_w7[j];
    int id = blockIdx.x;

    if (id < 3200) {
        // -------- scale 1 --------
        int b = id / 100, blk = id - 100 * b;
        int by0 = (blk / 10) * 96, bx0 = (blk % 10) * 96;
        float* T = sm;               // 57 x 102 raw tile (per phase)
        float* xn = sm + 57 * 102;   // 96 x 96 normalized block
        const float* im = X + (size_t)b * HW1 * HW1;
        int seg = warp / 3, strip = warp - seg * 3;
        int c = strip * 32 + lane;   // 0..95

#pragma unroll
        for (int phase = 0; phase < 2; phase++) {
            int rowbase = by0 - 3 + 48 * phase;
            for (int idx = tid; idx < 57 * 102; idx += NTHR) {
                int r = idx / 102, cc = idx - r * 102;
                int gy = rowbase + r; gy = gy < 0 ? 0 : (gy > 959 ? 959 : gy);
                int gx = bx0 + cc - 3; gx = gx < 0 ? 0 : (gx > 959 ? 959 : gx);
                T[idx] = __ldg(&im[gy * HW1 + gx]);
            }
            __syncthreads();
            int r0 = seg * 8;  // buffer-row origin; outputs local rows r0..r0+7
            float w1[7], w2[7];
#pragma unroll
            for (int j = 0; j < 14; j++) {
                const float* row = &T[(r0 + j) * 102 + c];
                float a1 = 0.f, a2 = 0.f;
#pragma unroll
                for (int t = 0; t < 7; t++) {
                    float v = row[t];
                    a1 = fmaf(w[t], v, a1);
                    a2 = fmaf(w[t], v * v, a2);
                }
                w1[j % 7] = a1; w2[j % 7] = a2;
                if (j >= 6) {
                    int rloc = r0 + j - 6;  // 0..47 within phase
                    float mu = 0.f, e2 = 0.f;
#pragma unroll
                    for (int i = 0; i < 7; i++) {
                        mu = fmaf(w[i], w1[(j - 6 + i) % 7], mu);
                        e2 = fmaf(w[i], w2[(j - 6 + i) % 7], e2);
                    }
                    float var = fmaxf(fabsf(e2 - mu * mu), 1e-30f);
                    float sig = fsqrt_ap(var);
                    float x = T[(rloc + 3) * 102 + c + 3];
                    xn[(48 * phase + rloc) * 96 + c] = fdiv_ap(x - mu, sig + 1.f);
                }
            }
            __syncthreads();
        }
        aggd_features(xn, 96, 96, 9216.f, b, blk, 0, tid, s_wsum, s_tot, s_par);
    } else {
        // -------- scale 2 --------
        int id2 = id - 3200;
        int b = id2 / 100, blk = id2 - 100 * b;
        int by0 = (blk / 10) * 48, bx0 = (blk % 10) * 48;
        float* Dh = sm;                    // 109 x 54 horizontal-downsampled rows
        float* T2 = Dh + 109 * 54;         // 54 x 54 downsampled tile (center -> xn)
        float* rX = T2 + 54 * 54;          // 54 x 48
        float* rX2 = rX + 54 * 48;         // 54 x 48
        const float* im = X + (size_t)b * HW1 * HW1;
        float w3a = g_w3[0], w3b = g_w3[1], w3c = g_w3[2];
        int rbase = 2 * by0 - 7;

        // horizontal 3-tap (zero pad on raw coords, clamp on downsampled col)
        for (int idx = tid; idx < 109 * 54; idx += NTHR) {
            int i = idx / 54, cc = idx - 54 * i;
            int ri = rbase + i;
            float s = 0.f;
            if (ri >= 0 && ri < 960) {
                int gxc = bx0 + cc - 3; gxc = gxc < 0 ? 0 : (gxc > 479 ? 479 : gxc);
                int sx = 2 * gxc - 1;
                const float* rp = &im[(size_t)ri * HW1];
                if (sx >= 0) s = fmaf(w3a, __ldg(&rp[sx]), s);
                s = fmaf(w3b, __ldg(&rp[sx + 1]), s);
                if (sx + 2 < 960) s = fmaf(w3c, __ldg(&rp[sx + 2]), s);
            }
            Dh[idx] = s;
        }
        __syncthreads();
        // vertical 3-tap (clamp on downsampled row)
        for (int idx = tid; idx < 54 * 54; idx += NTHR) {
            int r = idx / 54, cc = idx - 54 * r;
            int gyc = by0 + r - 3; gyc = gyc < 0 ? 0 : (gyc > 479 ? 479 : gyc);
            int row0 = 2 * (gyc - by0) + 6;  // buffer row of raw row 2*gyc-1
            const float* p = &Dh[row0 * 54 + cc];
            T2[idx] = fmaf(w3a, p[0], fmaf(w3b, p[54], w3c * p[108]));
        }
        __syncthreads();
        // MSCN horizontal 7-tap
        for (int idx = tid; idx < 54 * 48; idx += NTHR) {
            int r = idx / 48, cc = idx - 48 * r;
            const float* tr = &T2[r * 54 + cc];
            float a1 = 0.f, a2 = 0.f;
#pragma unroll
            for (int t = 0; t < 7; t++) {
                float v = tr[t];
                a1 = fmaf(w[t], v, a1);
                a2 = fmaf(w[t], v * v, a2);
            }
            rX[idx] = a1; rX2[idx] = a2;
        }
        __syncthreads();
        // vertical + normalize in place (owner-only center writes)
        for (int idx = tid; idx < 48 * 48; idx += NTHR) {
            int r = idx / 48, cc = idx - 48 * r;
            float mu = 0.f, e2 = 0.f;
#pragma unroll
            for (int i = 0; i < 7; i++) {
                mu = fmaf(w[i], rX[(r + i) * 48 + cc], mu);
                e2 = fmaf(w[i], rX2[(r + i) * 48 + cc], e2);
            }
            float var = fmaxf(fabsf(e2 - mu * mu), 1e-30f);
            float sig = fsqrt_ap(var);
            int ctr = (r + 3) * 54 + cc + 3;
            T2[ctr] = fdiv_ap(T2[ctr] - mu, sig + 1.f);
        }
        __syncthreads();
        aggd_features(&T2[3 * 54 + 3], 54, 48, 2304.f, b, blk, 18, tid, s_wsum, s_tot, s_par);
    }
}

// ---------------- final: mean/cov, Cholesky + fused forward solve ----------------
__global__ __launch_bounds__(256) void final_kernel(const float* __restrict__ mu_pris,
                                                    const float* __restrict__ cov_pris,
                                                    float* __restrict__ out) {
    __shared__ float sd[100 * 36];
    __shared__ float sM[36 * 37];
    __shared__ float smu[36], sdiff[36], sz[36];
    int b = blockIdx.x, tid = threadIdx.x;
    const int NT = 256;
    const float* fb = &g_feats[(size_t)b * 100 * 36];
    for (int i = tid; i < 3600; i += NT) sd[i] = fb[i];
    __syncthreads();
    if (tid < 36) {
        float s = 0.f;
        for (int n = 0; n < 100; n++) s += sd[n * 36 + tid];
        float m = s / 100.0f;
        smu[tid] = m;
        sdiff[tid] = mu_pris[tid] - m;
    }
    __syncthreads();
    for (int idx = tid; idx < 1296; idx += NT) {
        int f = idx / 36, g = idx - f * 36;
        if (g < f) continue;
        float mf = smu[f], mg = smu[g];
        float a0 = 0.f, a1 = 0.f, a2 = 0.f, a3 = 0.f;
        for (int n = 0; n < 100; n += 4) {
            a0 = fmaf(sd[n * 36 + f] - mf, sd[n * 36 + g] - mg, a0);
            a1 = fmaf(sd[(n + 1) * 36 + f] - mf, sd[(n + 1) * 36 + g] - mg, a1);
            a2 = fmaf(sd[(n + 2) * 36 + f] - mf, sd[(n + 2) * 36 + g] - mg, a2);
            a3 = fmaf(sd[(n + 3) * 36 + f] - mf, sd[(n + 3) * 36 + g] - mg, a3);
        }
        float s = ((a0 + a1) + (a2 + a3)) / 99.0f;
        float m = 0.5f * (cov_pris[idx] + s);
        sM[f * 37 + g] = m;
        sM[g * 37 + f] = m;
    }
    __syncthreads();
    for (int j = 0; j < 36; j++) {
        if (tid < 32) {
            float pd = 0.f, pz = 0.f;
            for (int k = tid; k < j; k += 32) {
                float l = sM[j * 37 + k];
                pd = fmaf(l, l, pd);
                pz = fmaf(l, sz[k], pz);
            }
#pragma unroll
            for (int off = 16; off > 0; off >>= 1) {
                pd += __shfl_down_sync(0xffffffffu, pd, off);
                pz += __shfl_down_sync(0xffffffffu, pz, off);
            }
            if (tid == 0) {
                float d = sqrtf(fmaxf(sM[j * 37 + j] - pd, 1e-20f));
                sM[j * 37 + j] = d;
                sz[j] = (sdiff[j] - pz) / d;
            }
        }
        __syncthreads();
        float dj = sM[j * 37 + j];
        for (int i = j + 1 + tid; i < 36; i += NT) {
            float s = sM[i * 37 + j];
            for (int k = 0; k < j; k++) s -= sM[i * 37 + k] * sM[j * 37 + k];
            sM[i * 37 + j] = s / dj;
        }
        __syncthreads();
    }
    if (tid == 0) {
        float q = 0.f;
        for (int i = 0; i < 36; i++) q += sz[i] * sz[i];
        out[b] = sqrtf(fmaxf(q, 0.f));
    }
}

// ---------------- launch ----------------
extern "C" void kernel_launch(void* const* d_in, const int* in_sizes, int n_in,
                              void* d_out, int out_size) {
    (void)in_sizes; (void)n_in; (void)out_size;
    const float* X = (const float*)d_in[0];
    const float* mu_pris = (const float*)d_in[1];
    const float* cov_pris = (const float*)d_in[2];
    float* out = (float*)d_out;

    const size_t smB = (size_t)(57 * 102 + 96 * 96) * sizeof(float);  // 60120 B
    cudaFuncSetAttribute(feat_kernel, cudaFuncAttributeMaxDynamicSharedMemorySize, (int)smB);

    init_tables_kernel<<<(NTAB + 255) / 256, 256>>>();
    feat_kernel<<<6400, NTHR, smB>>>(X);
    final_kernel<<<BATCH, 256>>>(mu_pris, cov_pris, out);
}

// round 5
// speedup vs baseline: 2.1871x; 1.1609x over previous
#include <cuda_runtime.h>
#include <cuda_fp16.h>
#include <math.h>

#define BATCH 32
#define HW1 960
#define NTAB 9801
#define NTHR 576
#define NW 18

// ---------------- device scratch ----------------
__device__ float g_rg[NTAB];   // AGGD r(gamma) table (monotone increasing)
__device__ float g_w7[7];      // 7-tap gaussian, sigma 7/6 (normalized)
__device__ float g_w3[3];      // 3-tap gaussian, sigma 0.5 (normalized, separable)
__device__ float g_feats[BATCH * 100 * 36];

static __device__ __forceinline__ float fsqrt_ap(float x) {
    float r; asm("sqrt.approx.f32 %0, %1;" : "=f"(r) : "f"(x)); return r;
}
static __device__ __forceinline__ float fdiv_ap(float a, float b) {
    float r; asm("div.approx.f32 %0, %1, %2;" : "=f"(r) : "f"(a), "f"(b)); return r;
}
// packed f32x2 helpers (Blackwell FFMA2): slot0=lo, slot1=hi
static __device__ __forceinline__ unsigned long long pack2(float a, float b) {
    unsigned long long r;
    asm("mov.b64 %0, {%1, %2};" : "=l"(r) : "f"(a), "f"(b));
    return r;
}
static __device__ __forceinline__ void unpack2(unsigned long long p, float& a, float& b) {
    asm("mov.b64 {%0, %1}, %2;" : "=f"(a), "=f"(b) : "l"(p));
}
static __device__ __forceinline__ unsigned long long ffma2(
    unsigned long long a, unsigned long long b, unsigned long long c) {
    unsigned long long d;
    asm("fma.rn.f32x2 %0, %1, %2, %3;" : "=l"(d) : "l"(a), "l"(b), "l"(c));
    return d;
}

// ---------------- init ----------------
__global__ void init_tables_kernel() {
    int i = blockIdx.x * blockDim.x + threadIdx.x;
    if (i < NTAB) {
        double g = 0.2 + 0.001 * (double)i;
        float a1 = (float)(1.0 / g), a2 = (float)(2.0 / g), a3 = (float)(3.0 / g);
        g_rg[i] = expf(2.f * lgammaf(a2) - lgammaf(a1) - lgammaf(a3));
    }
    if (i == 0) {
        double e[7], s = 0.0, sig = 7.0 / 6.0;
        for (int j = 0; j < 7; j++) {
            double ax = (double)j - 3.0;
            e[j] = exp(-(ax * ax) / (2.0 * sig * sig));
            s += e[j];
        }
        for (int j = 0; j < 7; j++) g_w7[j] = (float)(e[j] / s);
        double e3[3], s3 = 0.0;
        for (int j = 0; j < 3; j++) {
            double ax = (double)j - 1.0;
            e3[j] = exp(-(ax * ax) / 0.5);
            s3 += e3[j];
        }
        for (int j = 0; j < 3; j++) g_w3[j] = (float)(e3[j] / s3);
    }
}

// Warp-cooperative argmin over monotone table; first-index tie-break.
static __device__ __forceinline__ int argmin_table_warp(float t, int lane) {
    int lo = -1, hi = NTAB;
    while (hi - lo > 1) {
        int w = hi - lo - 1;
        int pos = lo + 1 + (int)(((unsigned)lane * (unsigned)w) >> 5);
        float v = __ldg(&g_rg[pos]);
        unsigned m = __ballot_sync(0xffffffffu, v < t);
        if (m == 0u) {
            hi = lo + 1;
        } else {
            int last = 31 - __clz(m);
            int nlo = __shfl_sync(0xffffffffu, pos, last);
            int nhi = hi;
            if (m != 0xffffffffu) {
                int first = __ffs(~m) - 1;
                nhi = __shfl_sync(0xffffffffu, pos, first);
            }
            lo = nlo; hi = nhi;
        }
    }
    int j = hi;
    if (j <= 0) return 0;
    if (j >= NTAB) return NTAB - 1;
    float d0 = fabsf(__ldg(&g_rg[j - 1]) - t);
    float d1 = fabsf(__ldg(&g_rg[j]) - t);
    return (d0 <= d1) ? (j - 1) : j;
}

static __device__ __forceinline__ float to_f32(float v) { return v; }
static __device__ __forceinline__ float to_f32(__half v) { return __half2float(v); }

// ---------------- AGGD stats + features from an xn block in smem ----------------
template <int BS, typename TX>
static __device__ __forceinline__ void aggd_features(
    const TX* xnb, int stride, float Nf, int b, int blk, int foff,
    int tid, float (*s_wsum)[20], float* s_tot, float* s_par) {
    int warp = tid >> 5, lane = tid & 31;
    float accf[15];
#pragma unroll
    for (int k = 0; k < 15; k++) accf[k] = 0.f;
    float cnt[5];
#pragma unroll
    for (int k = 0; k < 5; k++) cnt[k] = 0.f;
    for (int r = warp; r < BS; r += NW) {
        int rm = (r == 0) ? (BS - 1) : (r - 1);
        const TX* rowC = xnb + r * stride;
        const TX* rowM = xnb + rm * stride;
#pragma unroll
        for (int c0 = 0; c0 < BS; c0 += 32) {
            int c = c0 + lane;
            bool act = ((BS & 31) == 0) || (c < BS);
            int cs = act ? c : 0;
            int cm = (cs == 0) ? (BS - 1) : (cs - 1);
            int cpn = (cs == BS - 1) ? 0 : (cs + 1);
            float x0 = act ? to_f32(rowC[cs]) : 0.f;
            float y[5];
            y[0] = x0;
            y[1] = x0 * to_f32(rowC[cm]);
            y[2] = x0 * to_f32(rowM[cs]);
            y[3] = x0 * to_f32(rowM[cm]);
            y[4] = x0 * to_f32(rowM[cpn]);
#pragma unroll
            for (int s = 0; s < 5; s++) {
                float v = y[s];
                float fa = fabsf(v);
                accf[s * 3 + 0] = fmaf(v, v, accf[s * 3 + 0]);   // S2
                accf[s * 3 + 1] = fmaf(v, fa, accf[s * 3 + 1]);  // SV
                accf[s * 3 + 2] += fa;                            // SA
                if (v > 0.f) cnt[s] += 1.f;                       // CP
            }
        }
    }
#pragma unroll
    for (int k = 0; k < 15; k++)
#pragma unroll
        for (int off = 16; off > 0; off >>= 1)
            accf[k] += __shfl_down_sync(0xffffffffu, accf[k], off);
#pragma unroll
    for (int k = 0; k < 5; k++)
#pragma unroll
        for (int off = 16; off > 0; off >>= 1)
            cnt[k] += __shfl_down_sync(0xffffffffu, cnt[k], off);
    if (lane == 0) {
#pragma unroll
        for (int k = 0; k < 15; k++) s_wsum[warp][k] = accf[k];
#pragma unroll
        for (int s = 0; s < 5; s++) s_wsum[warp][15 + s] = cnt[s];
    }
    __syncthreads();
    if (tid < 20) {
        float s = 0.f;
        for (int wi = 0; wi < NW; wi++) s += s_wsum[wi][tid];
        s_tot[tid] = s;
    }
    __syncthreads();
    if (tid < 5) {
        float S2 = s_tot[tid * 3 + 0], SV = s_tot[tid * 3 + 1], SA = s_tot[tid * 3 + 2];
        float CP = s_tot[15 + tid];
        float SP2 = 0.5f * (S2 + SV);
        float SN2 = fmaxf(0.5f * (S2 - SV), 0.f);
        float CN = Nf - CP;
        float lstd = sqrtf(SN2 / fmaxf(CN, 1.f));
        float rstd = sqrtf(SP2 / fmaxf(CP, 1.f));
        s_par[5 + tid] = lstd;
        s_par[10 + tid] = rstd;
        float gh = lstd / fmaxf(rstd, 1e-12f);
        float ma = SA / Nf, ms = S2 / Nf;
        float rhat = (ma * ma) / fmaxf(ms, 1e-12f);
        float gh2 = gh * gh;
        s_par[tid] = rhat * (gh2 * gh + 1.f) * (gh + 1.f) / ((gh2 + 1.f) * (gh2 + 1.f));
    }
    __syncthreads();
    if (warp < 5) {
        int idxm = argmin_table_warp(s_par[warp], lane);
        if (lane == 0) {
            float alpha = (float)(0.2 + 0.001 * (double)idxm);
            float conv = expf(0.5f * (lgammaf(1.f / alpha) - lgammaf(3.f / alpha)));
            float bl = s_par[5 + warp] * conv, br = s_par[10 + warp] * conv;
            float* fo = &g_feats[((size_t)b * 100 + blk) * 36 + foff];
            if (warp == 0) {
                fo[0] = alpha;
                fo[1] = 0.5f * (bl + br);
            } else {
                int o = 2 + (warp - 1) * 4;
                fo[o] = alpha;
                fo[o + 1] = (br - bl) * expf(lgammaf(2.f / alpha) - lgammaf(1.f / alpha));
                fo[o + 2] = bl;
                fo[o + 3] = br;
            }
        }
    }
}

// ---------------- unified feature kernel ----------------
// ids 0..3199: scale 1 (96x96 blocks, single phase, fp16 xn)
// ids 3200..6399: scale 2 (separable fused downsample + 48x48 blocks)
__global__ __launch_bounds__(NTHR, 3) void feat_kernel(const float* __restrict__ X) {
    extern __shared__ float sm[];
    __shared__ float s_wsum[NW][20];
    __shared__ float s_tot[20];
    __shared__ float s_par[15];
    int tid = threadIdx.x, warp = tid >> 5, lane = tid & 31;
    int id = blockIdx.x;

    if (id < 3200) {
        // -------- scale 1: single phase, rolling packed conv --------
        int b = id / 100, blk = id - 100 * b;
        int by0 = (blk / 10) * 96, bx0 = (blk % 10) * 96;
        float* T = sm;                          // 102 x 102 raw tile
        __half* xn = (__half*)(sm + 102 * 102); // 96 x 96 normalized (fp16)
        const float* im = X + (size_t)b * HW1 * HW1;

        // load: warp->rows, lane->cols (no div/mod)
        for (int r = warp; r < 102; r += NW) {
            int gy = by0 + r - 3; gy = gy < 0 ? 0 : (gy > 959 ? 959 : gy);
            const float* rowp = im + (size_t)gy * HW1;
            float* trow = T + r * 102;
#pragma unroll
            for (int k = 0; k < 4; k++) {
                int c = lane + 32 * k;
                if (k < 3 || c < 102) {
                    int gx = bx0 + c - 3; gx = gx < 0 ? 0 : (gx > 959 ? 959 : gx);
                    trow[c] = __ldg(rowp + gx);
                }
            }
        }
        __syncthreads();

        // packed (x, x^2) separable conv; 6 segments x 16 output rows
        int seg = warp / 3, strip = warp - seg * 3;
        int c = strip * 32 + lane;   // 0..95
        int r0 = seg * 16;
        unsigned long long wp[7];
#pragma unroll
        for (int t = 0; t < 7; t++) { float wv = g_w7[t]; wp[t] = pack2(wv, wv); }
        unsigned long long ring[7];
#pragma unroll
        for (int j = 0; j < 22; j++) {
            const float* row = &T[(r0 + j) * 102 + c];
            unsigned long long acc = 0ull;
#pragma unroll
            for (int t = 0; t < 7; t++) {
                float v = row[t];
                acc = ffma2(wp[t], pack2(v, v * v), acc);
            }
            ring[j % 7] = acc;
            if (j >= 6) {
                unsigned long long me = 0ull;
#pragma unroll
                for (int i = 0; i < 7; i++) me = ffma2(wp[i], ring[(j - 6 + i) % 7], me);
                float mu, e2; unpack2(me, mu, e2);
                float var = fmaxf(fabsf(e2 - mu * mu), 1e-30f);
                float sig = fsqrt_ap(var);
                int rloc = r0 + j - 6;
                float x = T[(rloc + 3) * 102 + (c + 3)];
                xn[rloc * 96 + c] = __float2half(fdiv_ap(x - mu, sig + 1.f));
            }
        }
        __syncthreads();
        aggd_features<96>(xn, 96, 9216.f, b, blk, 0, tid, s_wsum, s_tot, s_par);
    } else {
        // -------- scale 2 --------
        int id2 = id - 3200;
        int b = id2 / 100, blk = id2 - 100 * b;
        int by0 = (blk / 10) * 48, bx0 = (blk % 10) * 48;
        float* Dh = sm;                    // 109 x 54 horizontal-downsampled rows
        float* T2 = Dh + 109 * 54;         // 54 x 54 downsampled tile (center -> xn)
        float* rX = T2 + 54 * 54;          // 54 x 48
        float* rX2 = rX + 54 * 48;         // 54 x 48
        const float* im = X + (size_t)b * HW1 * HW1;
        float w[7];
#pragma unroll
        for (int j = 0; j < 7; j++) w[j] = g_w7[j];
        float w3a = g_w3[0], w3b = g_w3[1], w3c = g_w3[2];
        int rbase = 2 * by0 - 7;

        // horizontal 3-tap (zero pad on raw coords, clamp on downsampled col)
        for (int idx = tid; idx < 109 * 54; idx += NTHR) {
            int i = idx / 54, cc = idx - 54 * i;
            int ri = rbase + i;
            float s = 0.f;
            if (ri >= 0 && ri < 960) {
                int gxc = bx0 + cc - 3; gxc = gxc < 0 ? 0 : (gxc > 479 ? 479 : gxc);
                int sx = 2 * gxc - 1;
                const float* rp = &im[(size_t)ri * HW1];
                if (sx >= 0) s = fmaf(w3a, __ldg(&rp[sx]), s);
                s = fmaf(w3b, __ldg(&rp[sx + 1]), s);
                if (sx + 2 < 960) s = fmaf(w3c, __ldg(&rp[sx + 2]), s);
            }
            Dh[idx] = s;
        }
        __syncthreads();
        // vertical 3-tap (clamp on downsampled row)
        for (int idx = tid; idx < 54 * 54; idx += NTHR) {
            int r = idx / 54, cc = idx - 54 * r;
            int gyc = by0 + r - 3; gyc = gyc < 0 ? 0 : (gyc > 479 ? 479 : gyc);
            int row0 = 2 * (gyc - by0) + 6;
            const float* p = &Dh[row0 * 54 + cc];
            T2[idx] = fmaf(w3a, p[0], fmaf(w3b, p[54], w3c * p[108]));
        }
        __syncthreads();
        // MSCN horizontal 7-tap
        for (int idx = tid; idx < 54 * 48; idx += NTHR) {
            int r = idx / 48, cc = idx - 48 * r;
            const float* tr = &T2[r * 54 + cc];
            float a1 = 0.f, a2 = 0.f;
#pragma unroll
            for (int t = 0; t < 7; t++) {
                float v = tr[t];
                a1 = fmaf(w[t], v, a1);
                a2 = fmaf(w[t], v * v, a2);
            }
            rX[idx] = a1; rX2[idx] = a2;
        }
        __syncthreads();
        // vertical + normalize in place (owner-only center writes)
        for (int idx = tid; idx < 48 * 48; idx += NTHR) {
            int r = idx / 48, cc = idx - 48 * r;
            float mu = 0.f, e2 = 0.f;
#pragma unroll
            for (int i = 0; i < 7; i++) {
                mu = fmaf(w[i], rX[(r + i) * 48 + cc], mu);
                e2 = fmaf(w[i], rX2[(r + i) * 48 + cc], e2);
            }
            float var = fmaxf(fabsf(e2 - mu * mu), 1e-30f);
            float sig = fsqrt_ap(var);
            int ctr = (r + 3) * 54 + cc + 3;
            T2[ctr] = fdiv_ap(T2[ctr] - mu, sig + 1.f);
        }
        __syncthreads();
        aggd_features<48>(&T2[3 * 54 + 3], 54, 2304.f, b, blk, 18, tid, s_wsum, s_tot, s_par);
    }
}

// ---------------- final: mean/cov, Cholesky + fused forward solve ----------------
__global__ __launch_bounds__(256) void final_kernel(const float* __restrict__ mu_pris,
                                                    const float* __restrict__ cov_pris,
                                                    float* __restrict__ out) {
    __shared__ float sd[100 * 36];
    __shared__ float sM[36 * 37];
    __shared__ float smu[36], sdiff[36], sz[36];
    int b = blockIdx.x, tid = threadIdx.x;
    const int NT = 256;
    const float* fb = &g_feats[(size_t)b * 100 * 36];
    for (int i = tid; i < 3600; i += NT) sd[i] = fb[i];
    __syncthreads();
    if (tid < 36) {
        float s = 0.f;
        for (int n = 0; n < 100; n++) s += sd[n * 36 + tid];
        float m = s / 100.0f;
        smu[tid] = m;
        sdiff[tid] = mu_pris[tid] - m;
    }
    __syncthreads();
    for (int idx = tid; idx < 1296; idx += NT) {
        int f = idx / 36, g = idx - f * 36;
        if (g < f) continue;
        float mf = smu[f], mg = smu[g];
        float a0 = 0.f, a1 = 0.f, a2 = 0.f, a3 = 0.f;
        for (int n = 0; n < 100; n += 4) {
            a0 = fmaf(sd[n * 36 + f] - mf, sd[n * 36 + g] - mg, a0);
            a1 = fmaf(sd[(n + 1) * 36 + f] - mf, sd[(n + 1) * 36 + g] - mg, a1);
            a2 = fmaf(sd[(n + 2) * 36 + f] - mf, sd[(n + 2) * 36 + g] - mg, a2);
            a3 = fmaf(sd[(n + 3) * 36 + f] - mf, sd[(n + 3) * 36 + g] - mg, a3);
        }
        float s = ((a0 + a1) + (a2 + a3)) / 99.0f;
        float m = 0.5f * (cov_pris[idx] + s);
        sM[f * 37 + g] = m;
        sM[g * 37 + f] = m;
    }
    __syncthreads();
    for (int j = 0; j < 36; j++) {
        if (tid < 32) {
            float pd = 0.f, pz = 0.f;
            for (int k = tid; k < j; k += 32) {
                float l = sM[j * 37 + k];
                pd = fmaf(l, l, pd);
                pz = fmaf(l, sz[k], pz);
            }
#pragma unroll
            for (int off = 16; off > 0; off >>= 1) {
                pd += __shfl_down_sync(0xffffffffu, pd, off);
                pz += __shfl_down_sync(0xffffffffu, pz, off);
            }
            if (tid == 0) {
                float d = sqrtf(fmaxf(sM[j * 37 + j] - pd, 1e-20f));
                sM[j * 37 + j] = d;
                sz[j] = (sdiff[j] - pz) / d;
            }
        }
        __syncthreads();
        float dj = sM[j * 37 + j];
        for (int i = j + 1 + tid; i < 36; i += NT) {
            float s = sM[i * 37 + j];
            for (int k = 0; k < j; k++) s -= sM[i * 37 + k] * sM[j * 37 + k];
            sM[i * 37 + j] = s / dj;
        }
        __syncthreads();
    }
    if (tid == 0) {
        float q = 0.f;
        for (int i = 0; i < 36; i++) q += sz[i] * sz[i];
        out[b] = sqrtf(fmaxf(q, 0.f));
    }
}

// ---------------- launch ----------------
extern "C" void kernel_launch(void* const* d_in, const int* in_sizes, int n_in,
                              void* d_out, int out_size) {
    (void)in_sizes; (void)n_in; (void)out_size;
    const float* X = (const float*)d_in[0];
    const float* mu_pris = (const float*)d_in[1];
    const float* cov_pris = (const float*)d_in[2];
    float* out = (float*)d_out;

    // scale-1: 102*102 f32 + 96*96 f16 = 60048 B (covers scale-2's 55944 B)
    const size_t smB = (size_t)(102 * 102) * sizeof(float) + (size_t)(96 * 96) * sizeof(__half);
    cudaFuncSetAttribute(feat_kernel, cudaFuncAttributeMaxDynamicSharedMemorySize, (int)smB);

    init_tables_kernel<<<(NTAB + 255) / 256, 256>>>();
    feat_kernel<<<6400, NTHR, smB>>>(X);
    final_kernel<<<BATCH, 256>>>(mu_pris, cov_pris, out);
}

// round 6
// speedup vs baseline: 2.3384x; 1.0692x over previous
#include <cuda_runtime.h>
#include <cuda_fp16.h>
#include <math.h>

#define BATCH 32
#define HW1 960
#define NTAB 9801
#define NTHR 576
#define NW 18

// ---------------- device scratch ----------------
__device__ float g_rg[NTAB];   // AGGD r(gamma) table (monotone increasing)
__device__ float g_w7[7];      // 7-tap gaussian, sigma 7/6 (normalized)
__device__ float g_w3[3];      // 3-tap gaussian, sigma 0.5 (normalized, separable)
__device__ float g_feats[BATCH * 100 * 36];

static __device__ __forceinline__ float fsqrt_ap(float x) {
    float r; asm("sqrt.approx.f32 %0, %1;" : "=f"(r) : "f"(x)); return r;
}
static __device__ __forceinline__ float fdiv_ap(float a, float b) {
    float r; asm("div.approx.f32 %0, %1, %2;" : "=f"(r) : "f"(a), "f"(b)); return r;
}
// packed f32x2 helpers (FFMA2): slot0=lo, slot1=hi
static __device__ __forceinline__ unsigned long long pack2(float a, float b) {
    unsigned long long r;
    asm("mov.b64 %0, {%1, %2};" : "=l"(r) : "f"(a), "f"(b));
    return r;
}
static __device__ __forceinline__ void unpack2(unsigned long long p, float& a, float& b) {
    asm("mov.b64 {%0, %1}, %2;" : "=f"(a), "=f"(b) : "l"(p));
}
static __device__ __forceinline__ unsigned long long ffma2(
    unsigned long long a, unsigned long long b, unsigned long long c) {
    unsigned long long d;
    asm("fma.rn.f32x2 %0, %1, %2, %3;" : "=l"(d) : "l"(a), "l"(b), "l"(c));
    return d;
}

// ---------------- init ----------------
__global__ void init_tables_kernel() {
    int i = blockIdx.x * blockDim.x + threadIdx.x;
    if (i < NTAB) {
        double g = 0.2 + 0.001 * (double)i;
        float a1 = (float)(1.0 / g), a2 = (float)(2.0 / g), a3 = (float)(3.0 / g);
        g_rg[i] = expf(2.f * lgammaf(a2) - lgammaf(a1) - lgammaf(a3));
    }
    if (i == 0) {
        double e[7], s = 0.0, sig = 7.0 / 6.0;
        for (int j = 0; j < 7; j++) {
            double ax = (double)j - 3.0;
            e[j] = exp(-(ax * ax) / (2.0 * sig * sig));
            s += e[j];
        }
        for (int j = 0; j < 7; j++) g_w7[j] = (float)(e[j] / s);
        double e3[3], s3 = 0.0;
        for (int j = 0; j < 3; j++) {
            double ax = (double)j - 1.0;
            e3[j] = exp(-(ax * ax) / 0.5);
            s3 += e3[j];
        }
        for (int j = 0; j < 3; j++) g_w3[j] = (float)(e3[j] / s3);
    }
}

// Warp-cooperative argmin over monotone table; first-index tie-break.
static __device__ __forceinline__ int argmin_table_warp(float t, int lane) {
    int lo = -1, hi = NTAB;
    while (hi - lo > 1) {
        int w = hi - lo - 1;
        int pos = lo + 1 + (int)(((unsigned)lane * (unsigned)w) >> 5);
        float v = __ldg(&g_rg[pos]);
        unsigned m = __ballot_sync(0xffffffffu, v < t);
        if (m == 0u) {
            hi = lo + 1;
        } else {
            int last = 31 - __clz(m);
            int nlo = __shfl_sync(0xffffffffu, pos, last);
            int nhi = hi;
            if (m != 0xffffffffu) {
                int first = __ffs(~m) - 1;
                nhi = __shfl_sync(0xffffffffu, pos, first);
            }
            lo = nlo; hi = nhi;
        }
    }
    int j = hi;
    if (j <= 0) return 0;
    if (j >= NTAB) return NTAB - 1;
    float d0 = fabsf(__ldg(&g_rg[j - 1]) - t);
    float d1 = fabsf(__ldg(&g_rg[j]) - t);
    return (d0 <= d1) ? (j - 1) : j;
}

static __device__ __forceinline__ float to_f32(float v) { return v; }
static __device__ __forceinline__ float to_f32(__half v) { return __half2float(v); }

// ---------------- AGGD stats + features from an xn block in smem ----------------
template <int BS, typename TX>
static __device__ __forceinline__ void aggd_features(
    const TX* xnb, int stride, float Nf, int b, int blk, int foff,
    int tid, float (*s_wsum)[20], float* s_tot, float* s_par) {
    int warp = tid >> 5, lane = tid & 31;
    float accf[15];
#pragma unroll
    for (int k = 0; k < 15; k++) accf[k] = 0.f;
    float cnt[5];
#pragma unroll
    for (int k = 0; k < 5; k++) cnt[k] = 0.f;
    for (int r = warp; r < BS; r += NW) {
        int rm = (r == 0) ? (BS - 1) : (r - 1);
        const TX* rowC = xnb + r * stride;
        const TX* rowM = xnb + rm * stride;
#pragma unroll
        for (int c0 = 0; c0 < BS; c0 += 32) {
            int c = c0 + lane;
            bool act = ((BS & 31) == 0) || (c < BS);
            int cs = act ? c : 0;
            int cm = (cs == 0) ? (BS - 1) : (cs - 1);
            int cpn = (cs == BS - 1) ? 0 : (cs + 1);
            float x0 = act ? to_f32(rowC[cs]) : 0.f;
            float y[5];
            y[0] = x0;
            y[1] = x0 * to_f32(rowC[cm]);
            y[2] = x0 * to_f32(rowM[cs]);
            y[3] = x0 * to_f32(rowM[cm]);
            y[4] = x0 * to_f32(rowM[cpn]);
#pragma unroll
            for (int s = 0; s < 5; s++) {
                float v = y[s];
                float fa = fabsf(v);
                accf[s * 3 + 0] = fmaf(v, v, accf[s * 3 + 0]);   // S2
                accf[s * 3 + 1] = fmaf(v, fa, accf[s * 3 + 1]);  // SV
                accf[s * 3 + 2] += fa;                            // SA
                if (v > 0.f) cnt[s] += 1.f;                       // CP
            }
        }
    }
#pragma unroll
    for (int k = 0; k < 15; k++)
#pragma unroll
        for (int off = 16; off > 0; off >>= 1)
            accf[k] += __shfl_down_sync(0xffffffffu, accf[k], off);
#pragma unroll
    for (int k = 0; k < 5; k++)
#pragma unroll
        for (int off = 16; off > 0; off >>= 1)
            cnt[k] += __shfl_down_sync(0xffffffffu, cnt[k], off);
    if (lane == 0) {
#pragma unroll
        for (int k = 0; k < 15; k++) s_wsum[warp][k] = accf[k];
#pragma unroll
        for (int s = 0; s < 5; s++) s_wsum[warp][15 + s] = cnt[s];
    }
    __syncthreads();
    if (tid < 20) {
        float s = 0.f;
        for (int wi = 0; wi < NW; wi++) s += s_wsum[wi][tid];
        s_tot[tid] = s;
    }
    __syncthreads();
    if (tid < 5) {
        float S2 = s_tot[tid * 3 + 0], SV = s_tot[tid * 3 + 1], SA = s_tot[tid * 3 + 2];
        float CP = s_tot[15 + tid];
        float SP2 = 0.5f * (S2 + SV);
        float SN2 = fmaxf(0.5f * (S2 - SV), 0.f);
        float CN = Nf - CP;
        float lstd = sqrtf(SN2 / fmaxf(CN, 1.f));
        float rstd = sqrtf(SP2 / fmaxf(CP, 1.f));
        s_par[5 + tid] = lstd;
        s_par[10 + tid] = rstd;
        float gh = lstd / fmaxf(rstd, 1e-12f);
        float ma = SA / Nf, ms = S2 / Nf;
        float rhat = (ma * ma) / fmaxf(ms, 1e-12f);
        float gh2 = gh * gh;
        s_par[tid] = rhat * (gh2 * gh + 1.f) * (gh + 1.f) / ((gh2 + 1.f) * (gh2 + 1.f));
    }
    __syncthreads();
    if (warp < 5) {
        int idxm = argmin_table_warp(s_par[warp], lane);
        if (lane == 0) {
            float alpha = (float)(0.2 + 0.001 * (double)idxm);
            float conv = expf(0.5f * (lgammaf(1.f / alpha) - lgammaf(3.f / alpha)));
            float bl = s_par[5 + warp] * conv, br = s_par[10 + warp] * conv;
            float* fo = &g_feats[((size_t)b * 100 + blk) * 36 + foff];
            if (warp == 0) {
                fo[0] = alpha;
                fo[1] = 0.5f * (bl + br);
            } else {
                int o = 2 + (warp - 1) * 4;
                fo[o] = alpha;
                fo[o + 1] = (br - bl) * expf(lgammaf(2.f / alpha) - lgammaf(1.f / alpha));
                fo[o + 2] = bl;
                fo[o + 3] = br;
            }
        }
    }
}

// ---------------- unified feature kernel ----------------
// ids 0..3199: scale 1 (96x96 blocks; float4 tile loads, packed rolling conv, fp16 xn)
// ids 3200..6399: scale 2 (register-fused downsample + 48x48 blocks)
__global__ __launch_bounds__(NTHR, 3) void feat_kernel(const float* __restrict__ X) {
    extern __shared__ float sm[];
    __shared__ float s_wsum[NW][20];
    __shared__ float s_tot[20];
    __shared__ float s_par[15];
    int tid = threadIdx.x, warp = tid >> 5, lane = tid & 31;
    int id = blockIdx.x;

    if (id < 3200) {
        // -------- scale 1 --------
        int b = id / 100, blk = id - 100 * b;
        int by0 = (blk / 10) * 96, bx0 = (blk % 10) * 96;
        const int TS = 104;                       // T row stride; logical col c at sc=c+1
        float* T = sm;                            // 102 x 104
        __half* xn = (__half*)(sm + 102 * TS);    // 96 x 96 normalized (fp16)
        const float* im = X + (size_t)b * HW1 * HW1;

        if (bx0 != 0 && bx0 != 864) {
            // interior in x: aligned float4 loads (bx0-3 ≡ 1 mod 4 → astart = bx0-4)
            int astart = bx0 - 4;
            for (int r = warp; r < 102; r += NW) {
                int gy = by0 + r - 3; gy = gy < 0 ? 0 : (gy > 959 ? 959 : gy);
                const float4* rowp = (const float4*)(im + (size_t)gy * HW1 + astart);
                if (lane < 26) {
                    float4 v = __ldg(rowp + lane);
                    *(float4*)&T[r * TS + 4 * lane] = v;
                }
            }
        } else {
            for (int r = warp; r < 102; r += NW) {
                int gy = by0 + r - 3; gy = gy < 0 ? 0 : (gy > 959 ? 959 : gy);
                const float* rowp = im + (size_t)gy * HW1;
#pragma unroll
                for (int k = 0; k < 4; k++) {
                    int c = lane + 32 * k;
                    if (k < 3 || c < 102) {
                        int gx = bx0 + c - 3; gx = gx < 0 ? 0 : (gx > 959 ? 959 : gx);
                        T[r * TS + c + 1] = __ldg(rowp + gx);
                    }
                }
            }
        }
        __syncthreads();

        // packed (x, x^2) separable conv; 6 segments x 16 output rows
        int seg = warp / 3, strip = warp - seg * 3;
        int c = strip * 32 + lane;   // 0..95
        int r0 = seg * 16;
        unsigned long long wp[7];
#pragma unroll
        for (int t = 0; t < 7; t++) { float wv = g_w7[t]; wp[t] = pack2(wv, wv); }
        unsigned long long ring[7];
#pragma unroll
        for (int j = 0; j < 22; j++) {
            const float* row = &T[(r0 + j) * TS + c + 1];
            unsigned long long acc = 0ull;
#pragma unroll
            for (int t = 0; t < 7; t++) {
                float v = row[t];
                acc = ffma2(wp[t], pack2(v, v * v), acc);
            }
            ring[j % 7] = acc;
            if (j >= 6) {
                unsigned long long me = 0ull;
#pragma unroll
                for (int i = 0; i < 7; i++) me = ffma2(wp[i], ring[(j - 6 + i) % 7], me);
                float mu, e2; unpack2(me, mu, e2);
                float var = fmaxf(fabsf(e2 - mu * mu), 1e-30f);
                float sig = fsqrt_ap(var);
                int rloc = r0 + j - 6;
                float x = T[(rloc + 3) * TS + (c + 4)];
                xn[rloc * 96 + c] = __float2half(fdiv_ap(x - mu, sig + 1.f));
            }
        }
        __syncthreads();
        aggd_features<96>(xn, 96, 9216.f, b, blk, 0, tid, s_wsum, s_tot, s_par);
    } else {
        // -------- scale 2 --------
        int id2 = id - 3200;
        int b = id2 / 100, blk = id2 - 100 * b;
        int by0 = (blk / 10) * 48, bx0 = (blk % 10) * 48;
        float* Dh = sm;                    // 109 x 54 horizontal-downsampled rows
        float* T2 = Dh + 109 * 54;         // 54 x 54 downsampled tile (center -> xn)
        float* rX = T2 + 54 * 54;          // 54 x 48
        float* rX2 = rX + 54 * 48;         // 54 x 48
        const float* im = X + (size_t)b * HW1 * HW1;
        float w[7];
#pragma unroll
        for (int j = 0; j < 7; j++) w[j] = g_w7[j];
        float w3a = g_w3[0], w3b = g_w3[1], w3c = g_w3[2];
        int rbase = 2 * by0 - 7;

        if (bx0 != 0 && bx0 != 432) {
            // interior in x: fused in-register horizontal downsample.
            // lane l loads raw rel cols 4l-1..4l+2 (astart2 = 2*bx0-8, aligned).
            int astart2 = 2 * bx0 - 8;
            for (int i = warp; i < 109; i += NW) {
                int ri = rbase + i;
                if (ri >= 0 && ri < 960) {
                    float4 v = make_float4(0.f, 0.f, 0.f, 0.f);
                    if (lane < 28)
                        v = __ldg((const float4*)(im + (size_t)ri * HW1 + astart2) + lane);
                    float nx = __shfl_down_sync(0xffffffffu, v.x, 1);
                    float ny = __shfl_down_sync(0xffffffffu, v.y, 1);
                    if (lane < 27) {
                        // out k=2l: taps rel 4l,4l+1,4l+2 ; k=2l+1: rel 4l+2,4l+3,4l+4
                        float o0 = fmaf(w3a, v.y, fmaf(w3b, v.z, w3c * v.w));
                        float o1 = fmaf(w3a, v.w, fmaf(w3b, nx, w3c * ny));
                        *(float2*)&Dh[i * 54 + 2 * lane] = make_float2(o0, o1);
                    }
                } else {
                    for (int k2 = lane; k2 < 54; k2 += 32) Dh[i * 54 + k2] = 0.f;
                }
            }
        } else {
            // border in x: scalar path with clamping/zero-pad
            for (int idx = tid; idx < 109 * 54; idx += NTHR) {
                int i = idx / 54, cc = idx - 54 * i;
                int ri = rbase + i;
                float s = 0.f;
                if (ri >= 0 && ri < 960) {
                    int gxc = bx0 + cc - 3; gxc = gxc < 0 ? 0 : (gxc > 479 ? 479 : gxc);
                    int sx = 2 * gxc - 1;
                    const float* rp = &im[(size_t)ri * HW1];
                    if (sx >= 0) s = fmaf(w3a, __ldg(&rp[sx]), s);
                    s = fmaf(w3b, __ldg(&rp[sx + 1]), s);
                    if (sx + 2 < 960) s = fmaf(w3c, __ldg(&rp[sx + 2]), s);
                }
                Dh[idx] = s;
            }
        }
        __syncthreads();
        // vertical 3-tap (clamp on downsampled row)
        for (int idx = tid; idx < 54 * 54; idx += NTHR) {
            int r = idx / 54, cc = idx - 54 * r;
            int gyc = by0 + r - 3; gyc = gyc < 0 ? 0 : (gyc > 479 ? 479 : gyc);
            int row0 = 2 * (gyc - by0) + 6;
            const float* p = &Dh[row0 * 54 + cc];
            T2[idx] = fmaf(w3a, p[0], fmaf(w3b, p[54], w3c * p[108]));
        }
        __syncthreads();
        // MSCN horizontal 7-tap
        for (int idx = tid; idx < 54 * 48; idx += NTHR) {
            int r = idx / 48, cc = idx - 48 * r;
            const float* tr = &T2[r * 54 + cc];
            float a1 = 0.f, a2 = 0.f;
#pragma unroll
            for (int t = 0; t < 7; t++) {
                float v = tr[t];
                a1 = fmaf(w[t], v, a1);
                a2 = fmaf(w[t], v * v, a2);
            }
            rX[idx] = a1; rX2[idx] = a2;
        }
        __syncthreads();
        // vertical + normalize in place (owner-only center writes)
        for (int idx = tid; idx < 48 * 48; idx += NTHR) {
            int r = idx / 48, cc = idx - 48 * r;
            float mu = 0.f, e2 = 0.f;
#pragma unroll
            for (int i = 0; i < 7; i++) {
                mu = fmaf(w[i], rX[(r + i) * 48 + cc], mu);
                e2 = fmaf(w[i], rX2[(r + i) * 48 + cc], e2);
            }
            float var = fmaxf(fabsf(e2 - mu * mu), 1e-30f);
            float sig = fsqrt_ap(var);
            int ctr = (r + 3) * 54 + cc + 3;
            T2[ctr] = fdiv_ap(T2[ctr] - mu, sig + 1.f);
        }
        __syncthreads();
        aggd_features<48>(&T2[3 * 54 + 3], 54, 2304.f, b, blk, 18, tid, s_wsum, s_tot, s_par);
    }
}

// ---------------- final: mean/cov, Cholesky + fused forward solve ----------------
__global__ __launch_bounds__(256) void final_kernel(const float* __restrict__ mu_pris,
                                                    const float* __restrict__ cov_pris,
                                                    float* __restrict__ out) {
    __shared__ float sd[100 * 36];
    __shared__ float sM[36 * 37];
    __shared__ float smu[36], sdiff[36], sz[36];
    int b = blockIdx.x, tid = threadIdx.x;
    const int NT = 256;
    const float* fb = &g_feats[(size_t)b * 100 * 36];
    for (int i = tid; i < 3600; i += NT) sd[i] = fb[i];
    __syncthreads();
    if (tid < 36) {
        float s = 0.f;
        for (int n = 0; n < 100; n++) s += sd[n * 36 + tid];
        float m = s / 100.0f;
        smu[tid] = m;
        sdiff[tid] = mu_pris[tid] - m;
    }
    __syncthreads();
    for (int idx = tid; idx < 1296; idx += NT) {
        int f = idx / 36, g = idx - f * 36;
        if (g < f) continue;
        float mf = smu[f], mg = smu[g];
        float a0 = 0.f, a1 = 0.f, a2 = 0.f, a3 = 0.f;
        for (int n = 0; n < 100; n += 4) {
            a0 = fmaf(sd[n * 36 + f] - mf, sd[n * 36 + g] - mg, a0);
            a1 = fmaf(sd[(n + 1) * 36 + f] - mf, sd[(n + 1) * 36 + g] - mg, a1);
            a2 = fmaf(sd[(n + 2) * 36 + f] - mf, sd[(n + 2) * 36 + g] - mg, a2);
            a3 = fmaf(sd[(n + 3) * 36 + f] - mf, sd[(n + 3) * 36 + g] - mg, a3);
        }
        float s = ((a0 + a1) + (a2 + a3)) / 99.0f;
        float m = 0.5f * (cov_pris[idx] + s);
        sM[f * 37 + g] = m;
        sM[g * 37 + f] = m;
    }
    __syncthreads();
    for (int j = 0; j < 36; j++) {
        if (tid < 32) {
            float pd = 0.f, pz = 0.f;
            for (int k = tid; k < j; k += 32) {
                float l = sM[j * 37 + k];
                pd = fmaf(l, l, pd);
                pz = fmaf(l, sz[k], pz);
            }
#pragma unroll
            for (int off = 16; off > 0; off >>= 1) {
                pd += __shfl_down_sync(0xffffffffu, pd, off);
                pz += __shfl_down_sync(0xffffffffu, pz, off);
            }
            if (tid == 0) {
                float d = sqrtf(fmaxf(sM[j * 37 + j] - pd, 1e-20f));
                sM[j * 37 + j] = d;
                sz[j] = (sdiff[j] - pz) / d;
            }
        }
        __syncthreads();
        float dj = sM[j * 37 + j];
        for (int i = j + 1 + tid; i < 36; i += NT) {
            float s = sM[i * 37 + j];
            for (int k = 0; k < j; k++) s -= sM[i * 37 + k] * sM[j * 37 + k];
            sM[i * 37 + j] = s / dj;
        }
        __syncthreads();
    }
    if (tid == 0) {
        float q = 0.f;
        for (int i = 0; i < 36; i++) q += sz[i] * sz[i];
        out[b] = sqrtf(fmaxf(q, 0.f));
    }
}

// ---------------- launch ----------------
extern "C" void kernel_launch(void* const* d_in, const int* in_sizes, int n_in,
                              void* d_out, int out_size) {
    (void)in_sizes; (void)n_in; (void)out_size;
    const float* X = (const float*)d_in[0];
    const float* mu_pris = (const float*)d_in[1];
    const float* cov_pris = (const float*)d_in[2];
    float* out = (float*)d_out;

    // scale-1: 102*104 f32 + 96*96 f16 = 60864 B (covers scale-2's 55944 B)
    const size_t smB = (size_t)(102 * 104) * sizeof(float) + (size_t)(96 * 96) * sizeof(__half);
    cudaFuncSetAttribute(feat_kernel, cudaFuncAttributeMaxDynamicSharedMemorySize, (int)smB);

    init_tables_kernel<<<(NTAB + 255) / 256, 256>>>();
    feat_kernel<<<6400, NTHR, smB>>>(X);
    final_kernel<<<BATCH, 256>>>(mu_pris, cov_pris, out);
}